// round 2
// baseline (speedup 1.0000x reference)
#include <cuda_runtime.h>

// ---------------- problem constants ----------------
#define N_NODES 20000
#define E_EDGES 640000
#define H_DIM   128
#define U_DIM   128
#define K0PAD   264      // 259 (2H+V) padded to multiple of 8 for the k-paired GEMM
#define TE      64       // edges (or nodes) per block

// ---------------- device scratch (no allocs allowed) ----------------
__device__ float g_W0T [128 * 264];   // phi_e_w0^T, k-padded
__device__ float g_W1T [128 * 128];
__device__ float g_Wx0T[128 * 128];
__device__ float g_Wx1T[128 * 128];
__device__ float g_Wh0T[128 * 256];
__device__ float g_Wh1T[128 * 128];
__device__ float g_Wh2T[128 * 128];
__device__ float g_WoutT[3 * 128];
__device__ float g_mAcc[N_NODES * 128]; // segment-sum of m_ij * gate
__device__ float g_vAcc[N_NODES * 9];   // segment-sum of shifts

// ---------------- packed f32x2 helpers ----------------
__device__ __forceinline__ unsigned long long fma2(unsigned long long a,
                                                   unsigned long long b,
                                                   unsigned long long c) {
    unsigned long long d;
    asm("fma.rn.f32x2 %0, %1, %2, %3;" : "=l"(d) : "l"(a), "l"(b), "l"(c));
    return d;
}
__device__ __forceinline__ float hadd2(unsigned long long a) {
    float lo, hi;
    asm("mov.b64 {%0,%1}, %2;" : "=f"(lo), "=f"(hi) : "l"(a));
    return lo + hi;
}
__device__ __forceinline__ void red_add_v4(float* p, float x, float y, float z, float w) {
    asm volatile("red.global.add.v4.f32 [%0], {%1,%2,%3,%4};"
                 :: "l"(p), "f"(x), "f"(y), "f"(z), "f"(w) : "memory");
}
__device__ __forceinline__ float silu(float v) {
    return v * (1.0f / (1.0f + __expf(-v)));
}

// ---------------- 64xK @ KT x128 GEMM, f32x2 along K ----------------
// sIn : [64][inStride] fp32, K columns valid (K multiple of 4, zero-padded)
// WT  : global, transposed weights [128][Kpad]
// sOut: [64][outStride], 128 output columns
// sW  : smem tile, 128*64 floats, chunk-rotated layout
// Thread map: lane -> output cols {lane, lane+32, lane+64, lane+96}
//             warp (tid>>5) -> 8 edge rows
__device__ __forceinline__ void gemm64(
    const float* sIn, int inStride,
    const float* __restrict__ WT, int Kpad, int K,
    const float* __restrict__ bias,
    float* sOut, int outStride, bool act,
    float* sW, int tid)
{
    const int lane = tid & 31;
    const int e0   = (tid >> 5) * 8;

    unsigned long long acc[8][4];
#pragma unroll
    for (int i = 0; i < 8; i++)
#pragma unroll
        for (int j = 0; j < 4; j++) acc[i][j] = 0ull;

    for (int k0 = 0; k0 < K; k0 += 64) {
        int kc = K - k0; if (kc > 64) kc = 64;
        const int n4 = kc >> 2;
        __syncthreads();   // protect sW reuse + make producer writes visible
        for (int idx = tid; idx < 128 * n4; idx += 256) {
            int o   = idx / n4;
            int kk4 = idx - o * n4;
            int pos = (kk4 + o) & 15;               // bank-rotation
            *(float4*)&sW[o * 64 + pos * 4] =
                *(const float4*)&WT[o * Kpad + k0 + kk4 * 4];
        }
        __syncthreads();
#pragma unroll 2
        for (int kk = 0; kk < kc; kk += 4) {
            const int kk4 = kk >> 2;
            ulonglong2 w[4];
#pragma unroll
            for (int j = 0; j < 4; j++) {
                int o   = lane + 32 * j;
                int pos = (kk4 + o) & 15;
                w[j] = *(const ulonglong2*)&sW[o * 64 + pos * 4];
            }
#pragma unroll
            for (int i = 0; i < 8; i++) {
                ulonglong2 x = *(const ulonglong2*)&sIn[(e0 + i) * inStride + k0 + kk];
#pragma unroll
                for (int j = 0; j < 4; j++) {
                    acc[i][j] = fma2(x.x, w[j].x, acc[i][j]);
                    acc[i][j] = fma2(x.y, w[j].y, acc[i][j]);
                }
            }
        }
    }

    float b[4];
#pragma unroll
    for (int j = 0; j < 4; j++) b[j] = bias[lane + 32 * j];
    __syncthreads();
#pragma unroll
    for (int i = 0; i < 8; i++) {
#pragma unroll
        for (int j = 0; j < 4; j++) {
            float v = hadd2(acc[i][j]) + b[j];
            if (act) v = silu(v);
            sOut[(e0 + i) * outStride + lane + 32 * j] = v;
        }
    }
}

// SMEM layout sizes (floats)
#define EDGE_SMEM_FLOATS (64*264 + 64*132 + 128*64 + 64*16 + 512 + 64 + 64)
#define NODE_SMEM_FLOATS (64*264 + 64*132 + 128*64)

// ---------------- edge kernel: fused phi_e / phi_x / phi_inf + scatters ----
extern "C" __global__ void __launch_bounds__(256, 1)
edge_kernel(const float* __restrict__ pos, const float* __restrict__ feat,
            const int* __restrict__ senders, const int* __restrict__ receivers,
            const float* __restrict__ b_e0, const float* __restrict__ b_e1,
            const float* __restrict__ b_x0, const float* __restrict__ b_x1,
            const float* __restrict__ b_xo, const float* __restrict__ w_inf,
            const float* __restrict__ b_inf)
{
    extern __shared__ float sm[];
    float* sX     = sm;                   // 64*264 (phi_e input, later aliased)
    float* sA     = sX + 64 * 264;        // 64*132 ping buffer
    float* sW     = sA + 64 * 132;        // 128*64 weight tile
    float* sVec   = sW + 128 * 64;        // 64*16: 9 vec comps + 3 lengths
    float* sSmall = sVec + 64 * 16;       // 384 WoutT + 128 winf
    float* sGate  = sSmall + 512;         // 64 gates
    int*   sRecv  = (int*)(sGate + 64);   // 64 receiver ids
    float* sM  = sX;                      // [64][132] alias (phi_e out)
    float* sP2 = sX + 64 * 132;           // [64][132] alias (phi_x torso out)

    const int tid   = threadIdx.x;
    const int eBase = blockIdx.x * TE;

    for (int i = tid; i < 384; i += 256) sSmall[i] = g_WoutT[i];
    for (int i = tid; i < 128; i += 256) sSmall[384 + i] = w_inf[i];

    // geometry per edge
    if (tid < 64) {
        const int e = eBase + tid;
        const int s = senders[e];
        const int r = receivers[e];
        sRecv[tid] = r;
        const float* ps = pos + s * 9;
        const float* pr = pos + r * 9;
#pragma unroll
        for (int v = 0; v < 3; v++) {
            float n2 = 0.f;
#pragma unroll
            for (int d = 0; d < 3; d++) {
                float dv = pr[v * 3 + d] - ps[v * 3 + d];
                sVec[tid * 16 + v * 3 + d] = dv;
                n2 += dv * dv;
            }
            sVec[tid * 16 + 9 + v] = (n2 > 0.f) ? sqrtf(n2) : 0.f;
            sX[tid * 264 + 256 + v] = n2;       // sq_lengths == n2
        }
#pragma unroll
        for (int k = 259; k < 264; k++) sX[tid * 264 + k] = 0.f;  // K padding
    }

    // feature gathers (all L2-resident)
    for (int idx = tid; idx < 64 * 64; idx += 256) {
        const int i = idx >> 6;
        const int q = idx & 63;
        const int e = eBase + i;
        if (q < 32) {
            const int s = senders[e];
            *(float4*)&sX[i * 264 + q * 4] = *(const float4*)&feat[s * 128 + q * 4];
        } else {
            const int r = receivers[e];
            *(float4*)&sX[i * 264 + 128 + (q - 32) * 4] =
                *(const float4*)&feat[r * 128 + (q - 32) * 4];
        }
    }
    __syncthreads();

    // phi_e (2 layers, silu) -> sM ; phi_x torso (2 layers, silu) -> sP2
    gemm64(sX, 264, g_W0T,  K0PAD, K0PAD, b_e0, sA,  132, true, sW, tid);
    gemm64(sA, 132, g_W1T,  128,   128,   b_e1, sM,  132, true, sW, tid);
    gemm64(sM, 132, g_Wx0T, 128,   128,   b_x0, sA,  132, true, sW, tid);
    gemm64(sA, 132, g_Wx1T, 128,   128,   b_x1, sP2, 132, true, sW, tid);
    __syncthreads();

    // phi_x final linear -> 3, shift scatter
    if (tid < 192) {
        const int i = tid / 3;
        const int v = tid - i * 3;
        const float* row = sP2 + i * 132;
        const float* wv  = sSmall + v * 128;
        float a0 = 0, a1 = 0, a2 = 0, a3 = 0;
#pragma unroll 8
        for (int k = 0; k < 128; k += 4) {
            a0 += row[k]     * wv[k];
            a1 += row[k + 1] * wv[k + 1];
            a2 += row[k + 2] * wv[k + 2];
            a3 += row[k + 3] * wv[k + 3];
        }
        const float phix = a0 + a1 + a2 + a3 + b_xo[v];
        const float len  = sVec[i * 16 + 9 + v];
        const float sc   = phix / (1.0f + len);
        const int   r    = sRecv[i];
#pragma unroll
        for (int d = 0; d < 3; d++)
            atomicAdd(&g_vAcc[r * 9 + v * 3 + d], sc * sVec[i * 16 + v * 3 + d]);
    }

    // phi_inf gate
    if (tid < 64) {
        const float* row = sM + tid * 132;
        const float* wv  = sSmall + 384;
        float a0 = 0, a1 = 0, a2 = 0, a3 = 0;
#pragma unroll 8
        for (int k = 0; k < 128; k += 4) {
            a0 += row[k]     * wv[k];
            a1 += row[k + 1] * wv[k + 1];
            a2 += row[k + 2] * wv[k + 2];
            a3 += row[k + 3] * wv[k + 3];
        }
        const float z = a0 + a1 + a2 + a3 + b_inf[0];
        sGate[tid] = 1.0f / (1.0f + __expf(-z));
    }
    __syncthreads();

    // m_i scatter: vectorized L2 reductions
    for (int idx = tid; idx < 64 * 32; idx += 256) {
        const int i = idx >> 5;
        const int c = (idx & 31) << 2;
        const float g = sGate[i];
        const float* row = sM + i * 132;
        const float4 m = *(const float4*)&row[c];
        red_add_v4(&g_mAcc[sRecv[i] * 128 + c], m.x * g, m.y * g, m.z * g, m.w * g);
    }
}

// ---------------- node kernel: phi_h + residuals + output ----------------
extern "C" __global__ void __launch_bounds__(256, 1)
node_kernel(const float* __restrict__ pos, const float* __restrict__ feat,
            const float* __restrict__ b_h0, const float* __restrict__ b_h1,
            const float* __restrict__ b_h2, float* __restrict__ out)
{
    extern __shared__ float sm[];
    float* sX  = sm;                 // 64*264
    float* sA  = sX + 64 * 264;      // 64*132
    float* sW  = sA + 64 * 132;      // 128*64
    float* sY2 = sX;                 // [64][132] alias after layer 1

    const int tid   = threadIdx.x;
    const int nBase = blockIdx.x * TE;
    const float invSq = 1.0f / sqrtf(19999.0f);

    for (int idx = tid; idx < 64 * 64; idx += 256) {
        const int i = idx >> 6;
        const int q = idx & 63;
        const int node = nBase + i;
        float4 v = make_float4(0.f, 0.f, 0.f, 0.f);
        if (node < N_NODES) {
            if (q < 32) {
                float4 m = *(const float4*)&g_mAcc[node * 128 + q * 4];
                v = make_float4(m.x * invSq, m.y * invSq, m.z * invSq, m.w * invSq);
            } else {
                v = *(const float4*)&feat[node * 128 + (q - 32) * 4];
            }
        }
        *(float4*)&sX[i * 264 + q * 4] = v;
    }
    for (int idx = tid; idx < 64 * 2; idx += 256) {
        const int i = idx >> 1;
        const int q = idx & 1;
        *(float4*)&sX[i * 264 + 256 + q * 4] = make_float4(0.f, 0.f, 0.f, 0.f);
    }
    __syncthreads();

    gemm64(sX,  264, g_Wh0T, 256, 256, b_h0, sA,  132, true,  sW, tid);
    gemm64(sA,  132, g_Wh1T, 128, 128, b_h1, sY2, 132, true,  sW, tid);
    gemm64(sY2, 132, g_Wh2T, 128, 128, b_h2, sA,  132, false, sW, tid);
    __syncthreads();

    // features_out = phi_h + residual
    for (int idx = tid; idx < 64 * 32; idx += 256) {
        const int i = idx >> 5;
        const int c = (idx & 31) << 2;
        const int node = nBase + i;
        if (node < N_NODES) {
            float4 h = *(const float4*)&sA[i * 132 + c];
            float4 f = *(const float4*)&feat[node * 128 + c];
            *(float4*)&out[(size_t)N_NODES * 9 + (size_t)node * 128 + c] =
                make_float4(h.x + f.x, h.y + f.y, h.z + f.z, h.w + f.w);
        }
    }
    // vectors_out = pos + shifts/(N-1)
    const float invNN = 1.0f / 19999.0f;
    for (int idx = tid; idx < 64 * 9; idx += 256) {
        const int i = idx / 9;
        const int c = idx - i * 9;
        const int node = nBase + i;
        if (node < N_NODES)
            out[node * 9 + c] = pos[node * 9 + c] + g_vAcc[node * 9 + c] * invNN;
    }
}

// ---------------- prep: transpose + pad weights ----------------
__global__ void prep_kernel(const float* __restrict__ w0, const float* __restrict__ w1,
                            const float* __restrict__ wx0, const float* __restrict__ wx1,
                            const float* __restrict__ wout,
                            const float* __restrict__ wh0, const float* __restrict__ wh1,
                            const float* __restrict__ wh2)
{
    const int idx    = blockIdx.x * blockDim.x + threadIdx.x;
    const int stride = gridDim.x * blockDim.x;
    for (int i = idx; i < 128 * 264; i += stride) {
        const int o = i / 264, k = i - o * 264;
        g_W0T[i] = (k < 259) ? w0[k * 128 + o] : 0.f;
    }
    for (int i = idx; i < 128 * 128; i += stride) {
        const int o = i >> 7, k = i & 127;
        g_W1T [i] = w1 [k * 128 + o];
        g_Wx0T[i] = wx0[k * 128 + o];
        g_Wx1T[i] = wx1[k * 128 + o];
        g_Wh1T[i] = wh1[k * 128 + o];
        g_Wh2T[i] = wh2[k * 128 + o];
    }
    for (int i = idx; i < 128 * 256; i += stride) {
        const int o = i >> 8, k = i & 255;
        g_Wh0T[i] = wh0[k * 128 + o];
    }
    for (int i = idx; i < 384; i += stride) {
        const int v = i >> 7, k = i & 127;
        g_WoutT[i] = wout[k * 3 + v];
    }
}

__global__ void zero_kernel()
{
    const int idx    = blockIdx.x * blockDim.x + threadIdx.x;
    const int stride = gridDim.x * blockDim.x;
    for (int i = idx; i < N_NODES * 128; i += stride) g_mAcc[i] = 0.f;
    for (int i = idx; i < N_NODES * 9;   i += stride) g_vAcc[i] = 0.f;
}

// ---------------- launch ----------------
extern "C" void kernel_launch(void* const* d_in, const int* in_sizes, int n_in,
                              void* d_out, int out_size)
{
    (void)in_sizes; (void)n_in; (void)out_size;
    const float* pos   = (const float*)d_in[0];
    const float* feat  = (const float*)d_in[1];
    const int* senders   = (const int*)d_in[2];
    const int* receivers = (const int*)d_in[3];
    const float* w_e0 = (const float*)d_in[4];  const float* b_e0 = (const float*)d_in[5];
    const float* w_e1 = (const float*)d_in[6];  const float* b_e1 = (const float*)d_in[7];
    const float* w_x0 = (const float*)d_in[8];  const float* b_x0 = (const float*)d_in[9];
    const float* w_x1 = (const float*)d_in[10]; const float* b_x1 = (const float*)d_in[11];
    const float* w_xo = (const float*)d_in[12]; const float* b_xo = (const float*)d_in[13];
    const float* w_if = (const float*)d_in[14]; const float* b_if = (const float*)d_in[15];
    const float* w_h0 = (const float*)d_in[16]; const float* b_h0 = (const float*)d_in[17];
    const float* w_h1 = (const float*)d_in[18]; const float* b_h1 = (const float*)d_in[19];
    const float* w_h2 = (const float*)d_in[20]; const float* b_h2 = (const float*)d_in[21];
    float* out = (float*)d_out;

    const size_t smemE = EDGE_SMEM_FLOATS * sizeof(float);
    const size_t smemN = NODE_SMEM_FLOATS * sizeof(float);
    cudaFuncSetAttribute(edge_kernel, cudaFuncAttributeMaxDynamicSharedMemorySize, (int)smemE);
    cudaFuncSetAttribute(node_kernel, cudaFuncAttributeMaxDynamicSharedMemorySize, (int)smemN);

    prep_kernel<<<128, 256>>>(w_e0, w_e1, w_x0, w_x1, w_xo, w_h0, w_h1, w_h2);
    zero_kernel<<<256, 256>>>();
    edge_kernel<<<E_EDGES / TE, 256, smemE>>>(pos, feat, senders, receivers,
                                              b_e0, b_e1, b_x0, b_x1, b_xo, w_if, b_if);
    node_kernel<<<(N_NODES + TE - 1) / TE, 256, smemN>>>(pos, feat, b_h0, b_h1, b_h2, out);
}

// round 5
// speedup vs baseline: 2.6720x; 2.6720x over previous
#include <cuda_runtime.h>
#include <cuda_fp16.h>
#include <cstdint>

#define N_NODES 20000
#define E_EDGES 640000
#define VOFF (N_NODES * 9)

// fragment-ordered weight tiles: [tile][hi:0..8191 | lo:8192..16383] u32 (2 fp16 each)
// tiles: 0=L0a 1=L0b 2=L1 3=Lx0 4=Lx1 5=H0a 6=H0b 7=H1 8=H2
__device__ __align__(16) uint32_t g_WF[9][16384];
__device__ float g_W0c[384];    // w_e0 rows 256..258, [v][out]
__device__ float g_Wout[384];   // phi_x_out_w^T [v][k]
__device__ __align__(16) float g_mAcc[N_NODES * 128];
__device__ __align__(16) float g_vAcc[N_NODES * 9];

// smem layout (float units): buf0 u32[16384] | buf1 u32[16384] | bias 1536 | vec 2048 | recv 128
#define SF_BIAS 32768
#define SF_VEC  34304
#define SF_RECV 36352
#define SMEM_BYTES (36480 * 4)

// ---------------- fast math (FMA-pipe only, no MUFU) ----------------
__device__ __forceinline__ float fast_exp(float x) {
    float y = fminf(fmaxf(x * 1.44269504f, -126.f), 126.f);
    int ni = __float2int_rn(y);
    float f = y - (float)ni;
    float p = 1.33978034e-3f;
    p = fmaf(p, f, 9.67518113e-3f);
    p = fmaf(p, f, 5.55042626e-2f);
    p = fmaf(p, f, 2.40226448e-1f);
    p = fmaf(p, f, 6.93147182e-1f);
    p = fmaf(p, f, 1.0f);
    return __int_as_float((ni + 127) << 23) * p;
}
__device__ __forceinline__ float fast_rcp(float d) {
    float r = __int_as_float(0x7EF127EAu - __float_as_int(d));
    r = r * (2.0f - d * r);
    r = r * (2.0f - d * r);
    r = r * (2.0f - d * r);
    return r;
}
__device__ __forceinline__ float fsilu(float x)    { return x * fast_rcp(1.0f + fast_exp(-x)); }
__device__ __forceinline__ float fsigmoid(float x) { return fast_rcp(1.0f + fast_exp(-x)); }

// ---------------- frag / mma helpers ----------------
__device__ __forceinline__ uint32_t smem_u32(const void* p) {
    uint32_t a;
    asm("{ .reg .u64 t; cvta.to.shared.u64 t, %1; cvt.u32.u64 %0, t; }" : "=r"(a) : "l"(p));
    return a;
}
__device__ __forceinline__ void split2(float x, float y, uint32_t& hi, uint32_t& lo) {
    __half2 h = __floats2half2_rn(x, y);
    float2 hf = __half22float2(h);
    __half2 l = __floats2half2_rn(x - hf.x, y - hf.y);
    hi = *reinterpret_cast<uint32_t*>(&h);
    lo = *reinterpret_cast<uint32_t*>(&l);
}
__device__ __forceinline__ void mma16816(float* d, const uint32_t* a, uint32_t b0, uint32_t b1) {
    asm volatile("mma.sync.aligned.m16n8k16.row.col.f32.f16.f16.f32 "
                 "{%0,%1,%2,%3}, {%4,%5,%6,%7}, {%8,%9}, {%0,%1,%2,%3};"
                 : "+f"(d[0]), "+f"(d[1]), "+f"(d[2]), "+f"(d[3])
                 : "r"(a[0]), "r"(a[1]), "r"(a[2]), "r"(a[3]), "r"(b0), "r"(b1));
}
// one 128x128x128 layer, 3-pass compensated (384 mma, 256 LDS.64)
// sw: base of one 16384-u32 tile buffer (hi at +0, lo at +8192)
__device__ __forceinline__ void layer_mma(float (&d)[16][4], const uint32_t (&ah)[8][4],
                                          const uint32_t (&al)[8][4], const uint32_t* sw, int lane) {
#pragma unroll
    for (int kc = 0; kc < 8; kc++) {
#pragma unroll
        for (int j = 0; j < 16; j++) {
            uint2 b = *(const uint2*)&sw[((kc * 16 + j) * 32 + lane) * 2];
            mma16816(d[j], ah[kc], b.x, b.y);
            mma16816(d[j], al[kc], b.x, b.y);
        }
    }
#pragma unroll
    for (int kc = 0; kc < 8; kc++) {
#pragma unroll
        for (int j = 0; j < 16; j++) {
            uint2 b = *(const uint2*)&sw[8192 + ((kc * 16 + j) * 32 + lane) * 2];
            mma16816(d[j], ah[kc], b.x, b.y);
        }
    }
}
__device__ __forceinline__ void zero_d(float (&d)[16][4]) {
#pragma unroll
    for (int j = 0; j < 16; j++)
#pragma unroll
        for (int q = 0; q < 4; q++) d[j][q] = 0.f;
}
__device__ __forceinline__ void loadW(uint32_t sAddr, const uint32_t* g, int tid) {
#pragma unroll 1
    for (int i = tid; i < 4096; i += 256)
        asm volatile("cp.async.cg.shared.global [%0], [%1], 16;"
                     :: "r"(sAddr + i * 16), "l"(g + i * 4));
    asm volatile("cp.async.commit_group;" ::: "memory");
}
__device__ __forceinline__ void waitW() {
    asm volatile("cp.async.wait_group 0;" ::: "memory");
}
__device__ __forceinline__ void red2(float* p, float x, float y) {
    asm volatile("red.global.add.v2.f32 [%0], {%1,%2};" :: "l"(p), "f"(x), "f"(y) : "memory");
}
// gather one K=16 chunk (2 rows) of fp32 features into A frags
__device__ __forceinline__ void gfrag(const float* f0, const float* f1, int kc, int tig,
                                      uint32_t (&ah)[8][4], uint32_t (&al)[8][4],
                                      bool v0, bool v1, float scale) {
    float2 z = make_float2(0.f, 0.f);
    float2 x0 = v0 ? __ldg((const float2*)(f0 + kc * 16 + 2 * tig)) : z;
    float2 x1 = v1 ? __ldg((const float2*)(f1 + kc * 16 + 2 * tig)) : z;
    float2 y0 = v0 ? __ldg((const float2*)(f0 + kc * 16 + 8 + 2 * tig)) : z;
    float2 y1 = v1 ? __ldg((const float2*)(f1 + kc * 16 + 8 + 2 * tig)) : z;
    split2(x0.x * scale, x0.y * scale, ah[kc][0], al[kc][0]);
    split2(x1.x * scale, x1.y * scale, ah[kc][1], al[kc][1]);
    split2(y0.x * scale, y0.y * scale, ah[kc][2], al[kc][2]);
    split2(y1.x * scale, y1.y * scale, ah[kc][3], al[kc][3]);
}

// ======================= edge kernel =======================
extern "C" __global__ void __launch_bounds__(256, 1)
edge_kernel(const float* __restrict__ pos, const float* __restrict__ feat,
            const int* __restrict__ senders, const int* __restrict__ receivers,
            const float* __restrict__ b_e0, const float* __restrict__ b_e1,
            const float* __restrict__ b_x0, const float* __restrict__ b_x1,
            const float* __restrict__ b_xo, const float* __restrict__ w_inf,
            const float* __restrict__ b_inf)
{
    extern __shared__ __align__(16) float sm[];
    const uint32_t sA = smem_u32(sm);
    const int tid = threadIdx.x, lane = tid & 31, warp = tid >> 5;
    const int g = lane >> 2, tig = lane & 3;
    const int r0 = warp * 16 + g, r1 = r0 + 8;
    const int eBase = blockIdx.x * 128;
    const uint32_t* sw0 = (const uint32_t*)sm;
    float* sBias = sm + SF_BIAS;
    float* sVec  = sm + SF_VEC;
    int*   sRecv = (int*)(sm + SF_RECV);

    loadW(sA, g_WF[0], tid);            // L0a -> buf0
    loadW(sA + 65536, g_WF[1], tid);    // L0b -> buf1

    for (int i = tid; i < 128; i += 256) {
        sBias[i] = b_e0[i]; sBias[128 + i] = b_e1[i];
        sBias[256 + i] = b_x0[i]; sBias[384 + i] = b_x1[i];
        sBias[512 + i] = w_inf[i];
    }
    for (int i = tid; i < 384; i += 256) { sBias[640 + i] = g_W0c[i]; sBias[1024 + i] = g_Wout[i]; }
    if (tid < 3) sBias[1408 + tid] = b_xo[tid];
    if (tid == 3) sBias[1411] = b_inf[0];

    if (tid < 128) {                     // per-edge geometry
        const int e = eBase + tid;
        const int s = senders[e], rc = receivers[e];
        sRecv[tid] = rc;
        const float* ps = pos + (size_t)s * 9;
        const float* pr = pos + (size_t)rc * 9;
        float* sv = sVec + tid * 16;
#pragma unroll
        for (int v = 0; v < 3; v++) {
            float n2 = 0.f;
#pragma unroll
            for (int dd = 0; dd < 3; dd++) {
                float dv = pr[v * 3 + dd] - ps[v * 3 + dd];
                sv[v * 3 + dd] = dv; n2 += dv * dv;
            }
            sv[9 + v] = (n2 > 0.f) ? sqrtf(n2) : 0.f;
            sv[12 + v] = n2;
        }
    }

    float d[16][4];
    uint32_t ah[8][4], al[8][4];
    const int e0 = eBase + r0, e1 = eBase + r1;

    {   // featS A-frags
        const float* f0 = feat + (size_t)senders[e0] * 128;
        const float* f1 = feat + (size_t)senders[e1] * 128;
#pragma unroll
        for (int kc = 0; kc < 8; kc++) gfrag(f0, f1, kc, tig, ah, al, true, true, 1.f);
    }
    waitW(); __syncthreads();

    zero_d(d);
    layer_mma(d, ah, al, sw0, lane);                 // L0a (featS x W0[0:128])
    __syncthreads();
    loadW(sA, g_WF[2], tid);                         // L1 -> buf0
    {   // featR A-frags
        const float* f0 = feat + (size_t)receivers[e0] * 128;
        const float* f1 = feat + (size_t)receivers[e1] * 128;
#pragma unroll
        for (int kc = 0; kc < 8; kc++) gfrag(f0, f1, kc, tig, ah, al, true, true, 1.f);
    }
    layer_mma(d, ah, al, sw0 + 16384, lane);         // L0b accumulate (buf1)

    {   // L0 epilogue: + bias + sq·w0c, silu -> frags
        const float* svr0 = sVec + r0 * 16;
        const float* svr1 = sVec + r1 * 16;
        float sa0 = svr0[12], sa1 = svr0[13], sa2 = svr0[14];
        float sb0 = svr1[12], sb1 = svr1[13], sb2 = svr1[14];
#pragma unroll
        for (int kc = 0; kc < 8; kc++)
#pragma unroll
            for (int u = 0; u < 2; u++) {
                int j = 2 * kc + u, c = j * 8 + 2 * tig;
                float2 bb = *(const float2*)(sBias + c);
                float2 w0 = *(const float2*)(sBias + 640 + c);
                float2 w1 = *(const float2*)(sBias + 768 + c);
                float2 w2 = *(const float2*)(sBias + 896 + c);
                float v0 = fsilu(d[j][0] + bb.x + sa0 * w0.x + sa1 * w1.x + sa2 * w2.x);
                float v1 = fsilu(d[j][1] + bb.y + sa0 * w0.y + sa1 * w1.y + sa2 * w2.y);
                float v2 = fsilu(d[j][2] + bb.x + sb0 * w0.x + sb1 * w1.x + sb2 * w2.x);
                float v3 = fsilu(d[j][3] + bb.y + sb0 * w0.y + sb1 * w1.y + sb2 * w2.y);
                split2(v0, v1, ah[kc][2 * u], al[kc][2 * u]);
                split2(v2, v3, ah[kc][2 * u + 1], al[kc][2 * u + 1]);
            }
    }
    waitW(); __syncthreads();
    loadW(sA + 65536, g_WF[3], tid);                 // Lx0 -> buf1
    zero_d(d);
    layer_mma(d, ah, al, sw0, lane);                 // L1 -> m_ij (buf0)

    {   // L1 epilogue: silu, gate dot, frags, m-scatter
        float s0 = 0.f, s1 = 0.f;
#pragma unroll
        for (int kc = 0; kc < 8; kc++)
#pragma unroll
            for (int u = 0; u < 2; u++) {
                int j = 2 * kc + u, c = j * 8 + 2 * tig;
                float2 bb = *(const float2*)(sBias + 128 + c);
                float2 wf = *(const float2*)(sBias + 512 + c);
                float v0 = fsilu(d[j][0] + bb.x), v1 = fsilu(d[j][1] + bb.y);
                float v2 = fsilu(d[j][2] + bb.x), v3 = fsilu(d[j][3] + bb.y);
                s0 += v0 * wf.x + v1 * wf.y;
                s1 += v2 * wf.x + v3 * wf.y;
                d[j][0] = v0; d[j][1] = v1; d[j][2] = v2; d[j][3] = v3;
                split2(v0, v1, ah[kc][2 * u], al[kc][2 * u]);
                split2(v2, v3, ah[kc][2 * u + 1], al[kc][2 * u + 1]);
            }
        s0 += __shfl_xor_sync(0xffffffffu, s0, 1); s0 += __shfl_xor_sync(0xffffffffu, s0, 2);
        s1 += __shfl_xor_sync(0xffffffffu, s1, 1); s1 += __shfl_xor_sync(0xffffffffu, s1, 2);
        const float bi = sBias[1411];
        const float g0 = fsigmoid(s0 + bi), g1 = fsigmoid(s1 + bi);
        float* p0 = g_mAcc + (size_t)sRecv[r0] * 128;
        float* p1 = g_mAcc + (size_t)sRecv[r1] * 128;
#pragma unroll
        for (int j = 0; j < 16; j++) {
            int c = j * 8 + 2 * tig;
            red2(p0 + c, d[j][0] * g0, d[j][1] * g0);
            red2(p1 + c, d[j][2] * g1, d[j][3] * g1);
        }
    }
    waitW(); __syncthreads();
    loadW(sA, g_WF[4], tid);                         // Lx1 -> buf0
    zero_d(d);
    layer_mma(d, ah, al, sw0 + 16384, lane);         // Lx0 (buf1)

    {   // Lx0 epilogue
#pragma unroll
        for (int kc = 0; kc < 8; kc++)
#pragma unroll
            for (int u = 0; u < 2; u++) {
                int j = 2 * kc + u, c = j * 8 + 2 * tig;
                float2 bb = *(const float2*)(sBias + 256 + c);
                float v0 = fsilu(d[j][0] + bb.x), v1 = fsilu(d[j][1] + bb.y);
                float v2 = fsilu(d[j][2] + bb.x), v3 = fsilu(d[j][3] + bb.y);
                split2(v0, v1, ah[kc][2 * u], al[kc][2 * u]);
                split2(v2, v3, ah[kc][2 * u + 1], al[kc][2 * u + 1]);
            }
    }
    waitW(); __syncthreads();
    zero_d(d);
    layer_mma(d, ah, al, sw0, lane);                 // Lx1 (buf0)

    {   // Lx1 epilogue: phi_x dots + shift scatter
        float pa0 = 0.f, pa1 = 0.f, pa2 = 0.f, pb0 = 0.f, pb1 = 0.f, pb2 = 0.f;
#pragma unroll
        for (int kc = 0; kc < 8; kc++)
#pragma unroll
            for (int u = 0; u < 2; u++) {
                int j = 2 * kc + u, c = j * 8 + 2 * tig;
                float2 bb = *(const float2*)(sBias + 384 + c);
                float2 q0 = *(const float2*)(sBias + 1024 + c);
                float2 q1 = *(const float2*)(sBias + 1152 + c);
                float2 q2 = *(const float2*)(sBias + 1280 + c);
                float v0 = fsilu(d[j][0] + bb.x), v1 = fsilu(d[j][1] + bb.y);
                float v2 = fsilu(d[j][2] + bb.x), v3 = fsilu(d[j][3] + bb.y);
                pa0 += v0 * q0.x + v1 * q0.y; pa1 += v0 * q1.x + v1 * q1.y; pa2 += v0 * q2.x + v1 * q2.y;
                pb0 += v2 * q0.x + v3 * q0.y; pb1 += v2 * q1.x + v3 * q1.y; pb2 += v2 * q2.x + v3 * q2.y;
            }
#pragma unroll
        for (int msk = 1; msk <= 2; msk <<= 1) {
            pa0 += __shfl_xor_sync(0xffffffffu, pa0, msk);
            pa1 += __shfl_xor_sync(0xffffffffu, pa1, msk);
            pa2 += __shfl_xor_sync(0xffffffffu, pa2, msk);
            pb0 += __shfl_xor_sync(0xffffffffu, pb0, msk);
            pb1 += __shfl_xor_sync(0xffffffffu, pb1, msk);
            pb2 += __shfl_xor_sync(0xffffffffu, pb2, msk);
        }
        if (tig == 0) {
            float pv0[3] = { pa0, pa1, pa2 }, pv1[3] = { pb0, pb1, pb2 };
            const float* svr0 = sVec + r0 * 16;
            const float* svr1 = sVec + r1 * 16;
            float* d0 = g_vAcc + (size_t)sRecv[r0] * 9;
            float* d1 = g_vAcc + (size_t)sRecv[r1] * 9;
#pragma unroll
            for (int v = 0; v < 3; v++) {
                float sc0 = (pv0[v] + sBias[1408 + v]) * fast_rcp(1.0f + svr0[9 + v]);
                float sc1 = (pv1[v] + sBias[1408 + v]) * fast_rcp(1.0f + svr1[9 + v]);
#pragma unroll
                for (int dd = 0; dd < 3; dd++) {
                    atomicAdd(d0 + v * 3 + dd, sc0 * svr0[v * 3 + dd]);
                    atomicAdd(d1 + v * 3 + dd, sc1 * svr1[v * 3 + dd]);
                }
            }
        }
    }
}

// ======================= node kernel =======================
extern "C" __global__ void __launch_bounds__(256, 1)
node_kernel(const float* __restrict__ pos, const float* __restrict__ feat,
            const float* __restrict__ b_h0, const float* __restrict__ b_h1,
            const float* __restrict__ b_h2, float* __restrict__ out)
{
    extern __shared__ __align__(16) float sm[];
    const uint32_t sA = smem_u32(sm);
    const int tid = threadIdx.x, lane = tid & 31, warp = tid >> 5;
    const int g = lane >> 2, tig = lane & 3;
    const int r0 = warp * 16 + g, r1 = r0 + 8;
    const int nBase = blockIdx.x * 128;
    const int node0 = nBase + r0, node1 = nBase + r1;
    const bool va = node0 < N_NODES, vb = node1 < N_NODES;
    const uint32_t* sw0 = (const uint32_t*)sm;
    float* sBias = sm + SF_BIAS;

    loadW(sA, g_WF[5], tid);            // H0a -> buf0
    loadW(sA + 65536, g_WF[6], tid);    // H0b -> buf1
    for (int i = tid; i < 128; i += 256) {
        sBias[i] = b_h0[i]; sBias[128 + i] = b_h1[i]; sBias[256 + i] = b_h2[i];
    }
    const float invNN = 1.0f / 19999.0f;
    for (int idx = tid; idx < 128 * 9; idx += 256) {
        const int i = idx / 9, c = idx - i * 9;
        const int n = nBase + i;
        if (n < N_NODES)
            out[(size_t)n * 9 + c] = pos[(size_t)n * 9 + c] + g_vAcc[(size_t)n * 9 + c] * invNN;
    }

    float d[16][4];
    uint32_t ah[8][4], al[8][4];
    const float invSq = rsqrtf(19999.0f);
    {   // m_i * invSq frags
        const float* f0 = g_mAcc + (size_t)(va ? node0 : 0) * 128;
        const float* f1 = g_mAcc + (size_t)(vb ? node1 : 0) * 128;
#pragma unroll
        for (int kc = 0; kc < 8; kc++) gfrag(f0, f1, kc, tig, ah, al, va, vb, invSq);
    }
    waitW(); __syncthreads();
    zero_d(d);
    layer_mma(d, ah, al, sw0, lane);                 // H0a (buf0)
    __syncthreads();
    loadW(sA, g_WF[7], tid);                         // H1 -> buf0
    {   // feat frags
        const float* f0 = feat + (size_t)(va ? node0 : 0) * 128;
        const float* f1 = feat + (size_t)(vb ? node1 : 0) * 128;
#pragma unroll
        for (int kc = 0; kc < 8; kc++) gfrag(f0, f1, kc, tig, ah, al, va, vb, 1.f);
    }
    layer_mma(d, ah, al, sw0 + 16384, lane);         // H0b accumulate (buf1)
#pragma unroll
    for (int kc = 0; kc < 8; kc++)                    // h0 epilogue
#pragma unroll
        for (int u = 0; u < 2; u++) {
            int j = 2 * kc + u, c = j * 8 + 2 * tig;
            float2 bb = *(const float2*)(sBias + c);
            float v0 = fsilu(d[j][0] + bb.x), v1 = fsilu(d[j][1] + bb.y);
            float v2 = fsilu(d[j][2] + bb.x), v3 = fsilu(d[j][3] + bb.y);
            split2(v0, v1, ah[kc][2 * u], al[kc][2 * u]);
            split2(v2, v3, ah[kc][2 * u + 1], al[kc][2 * u + 1]);
        }
    waitW(); __syncthreads();
    loadW(sA + 65536, g_WF[8], tid);                 // H2 -> buf1
    zero_d(d);
    layer_mma(d, ah, al, sw0, lane);                 // H1 (buf0)
#pragma unroll
    for (int kc = 0; kc < 8; kc++)                    // h1 epilogue
#pragma unroll
        for (int u = 0; u < 2; u++) {
            int j = 2 * kc + u, c = j * 8 + 2 * tig;
            float2 bb = *(const float2*)(sBias + 128 + c);
            float v0 = fsilu(d[j][0] + bb.x), v1 = fsilu(d[j][1] + bb.y);
            float v2 = fsilu(d[j][2] + bb.x), v3 = fsilu(d[j][3] + bb.y);
            split2(v0, v1, ah[kc][2 * u], al[kc][2 * u]);
            split2(v2, v3, ah[kc][2 * u + 1], al[kc][2 * u + 1]);
        }
    waitW(); __syncthreads();
    zero_d(d);
    layer_mma(d, ah, al, sw0 + 16384, lane);         // H2 (buf1)
    // h2 + residual -> out
#pragma unroll
    for (int j = 0; j < 16; j++) {
        int c = j * 8 + 2 * tig;
        float2 bb = *(const float2*)(sBias + 256 + c);
        if (va) {
            float2 f = __ldg((const float2*)(feat + (size_t)node0 * 128 + c));
            float2 o = make_float2(d[j][0] + bb.x + f.x, d[j][1] + bb.y + f.y);
            *(float2*)(out + VOFF + (size_t)node0 * 128 + c) = o;
        }
        if (vb) {
            float2 f = __ldg((const float2*)(feat + (size_t)node1 * 128 + c));
            float2 o = make_float2(d[j][2] + bb.x + f.x, d[j][3] + bb.y + f.y);
            *(float2*)(out + VOFF + (size_t)node1 * 128 + c) = o;
        }
    }
}

// ======================= prep + zero =======================
__global__ void prep_kernel(const float* __restrict__ w_e0, const float* __restrict__ w_e1,
                            const float* __restrict__ w_x0, const float* __restrict__ w_x1,
                            const float* __restrict__ w_xo,
                            const float* __restrict__ w_h0, const float* __restrict__ w_h1,
                            const float* __restrict__ w_h2)
{
    const int idx = blockIdx.x * blockDim.x + threadIdx.x;
    const int stride = gridDim.x * blockDim.x;
    const float* srcs[9] = { w_e0, w_e0, w_e1, w_x0, w_x1, w_h0, w_h0, w_h1, w_h2 };
    const int koff[9] = { 0, 128, 0, 0, 0, 0, 128, 0, 0 };
    for (int i = idx; i < 9 * 8192; i += stride) {
        const int t = i >> 13, fi = i & 8191;
        const int ri = fi & 1, ln = (fi >> 1) & 31, j = (fi >> 6) & 15, kc = fi >> 10;
        const int tg = ln & 3, gg = ln >> 2;
        const int k = kc * 16 + ri * 8 + tg * 2;
        const int n = j * 8 + gg;
        const float* s = srcs[t];
        const float wa = s[(size_t)(koff[t] + k) * 128 + n];
        const float wb = s[(size_t)(koff[t] + k + 1) * 128 + n];
        const __half ha = __float2half_rn(wa), hb = __float2half_rn(wb);
        const __half la = __float2half_rn(wa - __half2float(ha));
        const __half lb = __float2half_rn(wb - __half2float(hb));
        g_WF[t][fi] = (uint32_t)__half_as_ushort(ha) | ((uint32_t)__half_as_ushort(hb) << 16);
        g_WF[t][8192 + fi] = (uint32_t)__half_as_ushort(la) | ((uint32_t)__half_as_ushort(lb) << 16);
    }
    for (int i = idx; i < 384; i += stride) {
        const int v = i >> 7, k = i & 127;
        g_W0c[i]  = w_e0[(size_t)(256 + v) * 128 + k];
        g_Wout[i] = w_xo[(size_t)k * 3 + v];
    }
}

__global__ void zero_kernel()
{
    const int idx = blockIdx.x * blockDim.x + threadIdx.x;
    const int stride = gridDim.x * blockDim.x;
    for (int i = idx; i < N_NODES * 128; i += stride) g_mAcc[i] = 0.f;
    for (int i = idx; i < N_NODES * 9; i += stride)   g_vAcc[i] = 0.f;
}

// ======================= launch =======================
extern "C" void kernel_launch(void* const* d_in, const int* in_sizes, int n_in,
                              void* d_out, int out_size)
{
    (void)in_sizes; (void)n_in; (void)out_size;
    const float* pos  = (const float*)d_in[0];
    const float* feat = (const float*)d_in[1];
    const int* senders   = (const int*)d_in[2];
    const int* receivers = (const int*)d_in[3];
    const float* w_e0 = (const float*)d_in[4];  const float* b_e0 = (const float*)d_in[5];
    const float* w_e1 = (const float*)d_in[6];  const float* b_e1 = (const float*)d_in[7];
    const float* w_x0 = (const float*)d_in[8];  const float* b_x0 = (const float*)d_in[9];
    const float* w_x1 = (const float*)d_in[10]; const float* b_x1 = (const float*)d_in[11];
    const float* w_xo = (const float*)d_in[12]; const float* b_xo = (const float*)d_in[13];
    const float* w_if = (const float*)d_in[14]; const float* b_if = (const float*)d_in[15];
    const float* w_h0 = (const float*)d_in[16]; const float* b_h0 = (const float*)d_in[17];
    const float* w_h1 = (const float*)d_in[18]; const float* b_h1 = (const float*)d_in[19];
    const float* w_h2 = (const float*)d_in[20]; const float* b_h2 = (const float*)d_in[21];
    float* out = (float*)d_out;

    cudaFuncSetAttribute(edge_kernel, cudaFuncAttributeMaxDynamicSharedMemorySize, SMEM_BYTES);
    cudaFuncSetAttribute(node_kernel, cudaFuncAttributeMaxDynamicSharedMemorySize, SMEM_BYTES);

    prep_kernel<<<128, 256>>>(w_e0, w_e1, w_x0, w_x1, w_xo, w_h0, w_h1, w_h2);
    zero_kernel<<<256, 256>>>();
    edge_kernel<<<E_EDGES / 128, 256, SMEM_BYTES>>>(pos, feat, senders, receivers,
                                                    b_e0, b_e1, b_x0, b_x1, b_xo, w_if, b_if);
    node_kernel<<<(N_NODES + 127) / 128, 256, SMEM_BYTES>>>(pos, feat, b_h0, b_h1, b_h2, out);
}

// round 6
// speedup vs baseline: 3.1574x; 1.1817x over previous
#include <cuda_runtime.h>
#include <cuda_fp16.h>
#include <cstdint>

#define N_NODES 20000
#define E_EDGES 640000
#define VOFF (N_NODES * 9)

// fragment-ordered weight tiles: [tile][hi:0..8191 | lo:8192..16383] u32 (2 fp16 each)
// tiles: 0=L0a 1=L0b 2=L1 3=Lx0 4=Lx1 5=H0a 6=H0b 7=H1 8=H2
__device__ __align__(16) uint32_t g_WF[9][16384];
__device__ float g_W0c[384];    // w_e0 rows 256..258, [v][out]
__device__ float g_Wout[384];   // phi_x_out_w^T [v][k]
__device__ __align__(16) float g_mAcc[N_NODES * 128];
__device__ __align__(16) float g_vAcc[N_NODES * 9];

// smem (float units): buf0 u32[8192] | buf1 u32[8192] | buf2 u32[8192] | bias 1536 | vec 1024 | recv 64
#define SF_BIAS 24576
#define SF_VEC  26112
#define SF_RECV 27136
#define SMEM_BYTES (27200 * 4)

// ---------------- fast activations: MUFU ex2/rcp (tensor era: MUFU pipe is idle) ----
__device__ __forceinline__ float fsilu(float x) {
    float e; asm("ex2.approx.f32 %0, %1;" : "=f"(e) : "f"(x * -1.44269504f));
    float r; asm("rcp.approx.f32 %0, %1;" : "=f"(r) : "f"(1.0f + e));
    return x * r;
}
__device__ __forceinline__ float fsigmoid(float x) {
    float e; asm("ex2.approx.f32 %0, %1;" : "=f"(e) : "f"(x * -1.44269504f));
    float r; asm("rcp.approx.f32 %0, %1;" : "=f"(r) : "f"(1.0f + e));
    return r;
}
__device__ __forceinline__ float frcp(float d) {
    float r; asm("rcp.approx.f32 %0, %1;" : "=f"(r) : "f"(d));
    return r;
}

// ---------------- frag / mma helpers ----------------
__device__ __forceinline__ uint32_t smem_u32(const void* p) {
    uint32_t a;
    asm("{ .reg .u64 t; cvta.to.shared.u64 t, %1; cvt.u32.u64 %0, t; }" : "=r"(a) : "l"(p));
    return a;
}
__device__ __forceinline__ void split2(float x, float y, uint32_t& hi, uint32_t& lo) {
    __half2 h = __floats2half2_rn(x, y);
    float2 hf = __half22float2(h);
    __half2 l = __floats2half2_rn(x - hf.x, y - hf.y);
    hi = *reinterpret_cast<uint32_t*>(&h);
    lo = *reinterpret_cast<uint32_t*>(&l);
}
__device__ __forceinline__ void mma16816(float* d, const uint32_t* a, uint32_t b0, uint32_t b1) {
    asm volatile("mma.sync.aligned.m16n8k16.row.col.f32.f16.f16.f32 "
                 "{%0,%1,%2,%3}, {%4,%5,%6,%7}, {%8,%9}, {%0,%1,%2,%3};"
                 : "+f"(d[0]), "+f"(d[1]), "+f"(d[2]), "+f"(d[3])
                 : "r"(a[0]), "r"(a[1]), "r"(a[2]), "r"(a[3]), "r"(b0), "r"(b1));
}
// passes 1+2 (ah*Whi + al*Whi) over a 32KB hi buffer
__device__ __forceinline__ void mma12(float (&d)[16][4], const uint32_t (&ah)[8][4],
                                      const uint32_t (&al)[8][4], const uint32_t* swHi, int lane) {
#pragma unroll
    for (int kc = 0; kc < 8; kc++)
#pragma unroll
        for (int j = 0; j < 16; j++) {
            uint2 b = *(const uint2*)&swHi[((kc * 16 + j) * 32 + lane) * 2];
            mma16816(d[j], ah[kc], b.x, b.y);
            mma16816(d[j], al[kc], b.x, b.y);
        }
}
// pass 3 (ah*Wlo) over a 32KB lo buffer
__device__ __forceinline__ void mma3(float (&d)[16][4], const uint32_t (&ah)[8][4],
                                     const uint32_t* swLo, int lane) {
#pragma unroll
    for (int kc = 0; kc < 8; kc++)
#pragma unroll
        for (int j = 0; j < 16; j++) {
            uint2 b = *(const uint2*)&swLo[((kc * 16 + j) * 32 + lane) * 2];
            mma16816(d[j], ah[kc], b.x, b.y);
        }
}
__device__ __forceinline__ void zero_d(float (&d)[16][4]) {
#pragma unroll
    for (int j = 0; j < 16; j++)
#pragma unroll
        for (int q = 0; q < 4; q++) d[j][q] = 0.f;
}
// load one 32KB half-tile (2048 x 16B), own commit group
__device__ __forceinline__ void loadW32(uint32_t sAddr, const uint32_t* g, int tid) {
#pragma unroll 1
    for (int i = tid; i < 2048; i += 128)
        asm volatile("cp.async.cg.shared.global [%0], [%1], 16;"
                     :: "r"(sAddr + i * 16), "l"(g + i * 4));
    asm volatile("cp.async.commit_group;" ::: "memory");
}
__device__ __forceinline__ void waitW0() { asm volatile("cp.async.wait_group 0;" ::: "memory"); }
__device__ __forceinline__ void waitW1() { asm volatile("cp.async.wait_group 1;" ::: "memory"); }
__device__ __forceinline__ void red2(float* p, float x, float y) {
    asm volatile("red.global.add.v2.f32 [%0], {%1,%2};" :: "l"(p), "f"(x), "f"(y) : "memory");
}
// gather one K=16 chunk (2 rows) of fp32 features into A frags
__device__ __forceinline__ void gfrag(const float* f0, const float* f1, int kc, int tig,
                                      uint32_t (&ah)[8][4], uint32_t (&al)[8][4],
                                      bool v0, bool v1, float scale) {
    float2 z = make_float2(0.f, 0.f);
    float2 x0 = v0 ? __ldg((const float2*)(f0 + kc * 16 + 2 * tig)) : z;
    float2 x1 = v1 ? __ldg((const float2*)(f1 + kc * 16 + 2 * tig)) : z;
    float2 y0 = v0 ? __ldg((const float2*)(f0 + kc * 16 + 8 + 2 * tig)) : z;
    float2 y1 = v1 ? __ldg((const float2*)(f1 + kc * 16 + 8 + 2 * tig)) : z;
    split2(x0.x * scale, x0.y * scale, ah[kc][0], al[kc][0]);
    split2(x1.x * scale, x1.y * scale, ah[kc][1], al[kc][1]);
    split2(y0.x * scale, y0.y * scale, ah[kc][2], al[kc][2]);
    split2(y1.x * scale, y1.y * scale, ah[kc][3], al[kc][3]);
}

// ======================= edge kernel: 64 edges / 4 warps / 2 blocks per SM =========
extern "C" __global__ void __launch_bounds__(128, 2)
edge_kernel(const float* __restrict__ pos, const float* __restrict__ feat,
            const int* __restrict__ senders, const int* __restrict__ receivers,
            const float* __restrict__ b_e0, const float* __restrict__ b_e1,
            const float* __restrict__ b_x0, const float* __restrict__ b_x1,
            const float* __restrict__ b_xo, const float* __restrict__ w_inf,
            const float* __restrict__ b_inf)
{
    extern __shared__ __align__(16) float sm[];
    const uint32_t sA = smem_u32(sm);
    const int tid = threadIdx.x, lane = tid & 31, warp = tid >> 5;
    const int g = lane >> 2, tig = lane & 3;
    const int r0 = warp * 16 + g, r1 = r0 + 8;      // rows 0..63
    const int eBase = blockIdx.x * 64;
    const uint32_t* B0 = (const uint32_t*)sm;
    const uint32_t* B1 = B0 + 8192;
    const uint32_t* B2 = B0 + 16384;
    const uint32_t a0 = sA, a1 = sA + 32768, a2 = sA + 65536;
    float* sBias = sm + SF_BIAS;
    float* sVec  = sm + SF_VEC;
    int*   sRecv = (int*)(sm + SF_RECV);

    loadW32(a0, g_WF[0], tid);           // T0.hi
    loadW32(a1, g_WF[0] + 8192, tid);    // T0.lo
    loadW32(a2, g_WF[1], tid);           // T1.hi (prefetch)

    for (int i = tid; i < 128; i += 128) {
        sBias[i] = b_e0[i]; sBias[128 + i] = b_e1[i];
        sBias[256 + i] = b_x0[i]; sBias[384 + i] = b_x1[i];
        sBias[512 + i] = w_inf[i];
    }
    for (int i = tid; i < 384; i += 128) { sBias[640 + i] = g_W0c[i]; sBias[1024 + i] = g_Wout[i]; }
    if (tid < 3) sBias[1408 + tid] = b_xo[tid];
    if (tid == 3) sBias[1411] = b_inf[0];

    if (tid < 64) {                      // per-edge geometry
        const int e = eBase + tid;
        const int s = senders[e], rc = receivers[e];
        sRecv[tid] = rc;
        const float* ps = pos + (size_t)s * 9;
        const float* pr = pos + (size_t)rc * 9;
        float* sv = sVec + tid * 16;
#pragma unroll
        for (int v = 0; v < 3; v++) {
            float n2 = 0.f;
#pragma unroll
            for (int dd = 0; dd < 3; dd++) {
                float dv = pr[v * 3 + dd] - ps[v * 3 + dd];
                sv[v * 3 + dd] = dv; n2 += dv * dv;
            }
            sv[9 + v] = (n2 > 0.f) ? sqrtf(n2) : 0.f;
            sv[12 + v] = n2;
        }
    }

    float d[16][4];
    uint32_t ah[8][4], al[8][4];
    const int e0 = eBase + r0, e1 = eBase + r1;

    {   // featS A-frags
        const float* f0 = feat + (size_t)senders[e0] * 128;
        const float* f1 = feat + (size_t)senders[e1] * 128;
#pragma unroll
        for (int kc = 0; kc < 8; kc++) gfrag(f0, f1, kc, tig, ah, al, true, true, 1.f);
    }
    waitW1(); __syncthreads();           // T0.hi/lo ready (T1.hi may be in flight)

    // ---- T0 = L0a (featS), rotation (0,1,2) ----
    zero_d(d);
    mma12(d, ah, al, B0, lane);
    __syncthreads();
    loadW32(a0, g_WF[1] + 8192, tid);    // T1.lo -> b0
    mma3(d, ah, B1, lane);
    {   // featR A-frags (after ah consumed)
        const float* f0 = feat + (size_t)receivers[e0] * 128;
        const float* f1 = feat + (size_t)receivers[e1] * 128;
#pragma unroll
        for (int kc = 0; kc < 8; kc++) gfrag(f0, f1, kc, tig, ah, al, true, true, 1.f);
    }
    waitW0(); __syncthreads();

    // ---- T1 = L0b (featR, accumulate), rotation (2,0,1) ----
    loadW32(a1, g_WF[2], tid);           // T2.hi -> b1
    mma12(d, ah, al, B2, lane);
    __syncthreads();
    loadW32(a2, g_WF[2] + 8192, tid);    // T2.lo -> b2
    mma3(d, ah, B0, lane);
    {   // L0 epilogue: + bias + sq·w0c, silu -> frags
        const float* svr0 = sVec + r0 * 16;
        const float* svr1 = sVec + r1 * 16;
        float sa0 = svr0[12], sa1 = svr0[13], sa2 = svr0[14];
        float sb0 = svr1[12], sb1 = svr1[13], sb2 = svr1[14];
#pragma unroll
        for (int kc = 0; kc < 8; kc++)
#pragma unroll
            for (int u = 0; u < 2; u++) {
                int j = 2 * kc + u, c = j * 8 + 2 * tig;
                float2 bb = *(const float2*)(sBias + c);
                float2 w0 = *(const float2*)(sBias + 640 + c);
                float2 w1 = *(const float2*)(sBias + 768 + c);
                float2 w2 = *(const float2*)(sBias + 896 + c);
                float v0 = fsilu(d[j][0] + bb.x + sa0 * w0.x + sa1 * w1.x + sa2 * w2.x);
                float v1 = fsilu(d[j][1] + bb.y + sa0 * w0.y + sa1 * w1.y + sa2 * w2.y);
                float v2 = fsilu(d[j][2] + bb.x + sb0 * w0.x + sb1 * w1.x + sb2 * w2.x);
                float v3 = fsilu(d[j][3] + bb.y + sb0 * w0.y + sb1 * w1.y + sb2 * w2.y);
                split2(v0, v1, ah[kc][2 * u], al[kc][2 * u]);
                split2(v2, v3, ah[kc][2 * u + 1], al[kc][2 * u + 1]);
            }
    }
    waitW0(); __syncthreads();

    // ---- T2 = L1 -> m_ij, rotation (1,2,0) ----
    loadW32(a0, g_WF[3], tid);           // T3.hi -> b0
    zero_d(d);
    mma12(d, ah, al, B1, lane);
    __syncthreads();
    loadW32(a1, g_WF[3] + 8192, tid);    // T3.lo -> b1
    mma3(d, ah, B2, lane);
    {   // L1 epilogue: silu, gate dot, frags, m-scatter
        float s0 = 0.f, s1 = 0.f;
#pragma unroll
        for (int kc = 0; kc < 8; kc++)
#pragma unroll
            for (int u = 0; u < 2; u++) {
                int j = 2 * kc + u, c = j * 8 + 2 * tig;
                float2 bb = *(const float2*)(sBias + 128 + c);
                float2 wf = *(const float2*)(sBias + 512 + c);
                float v0 = fsilu(d[j][0] + bb.x), v1 = fsilu(d[j][1] + bb.y);
                float v2 = fsilu(d[j][2] + bb.x), v3 = fsilu(d[j][3] + bb.y);
                s0 += v0 * wf.x + v1 * wf.y;
                s1 += v2 * wf.x + v3 * wf.y;
                d[j][0] = v0; d[j][1] = v1; d[j][2] = v2; d[j][3] = v3;
                split2(v0, v1, ah[kc][2 * u], al[kc][2 * u]);
                split2(v2, v3, ah[kc][2 * u + 1], al[kc][2 * u + 1]);
            }
        s0 += __shfl_xor_sync(0xffffffffu, s0, 1); s0 += __shfl_xor_sync(0xffffffffu, s0, 2);
        s1 += __shfl_xor_sync(0xffffffffu, s1, 1); s1 += __shfl_xor_sync(0xffffffffu, s1, 2);
        const float bi = sBias[1411];
        const float g0 = fsigmoid(s0 + bi), g1 = fsigmoid(s1 + bi);
        float* p0 = g_mAcc + (size_t)sRecv[r0] * 128;
        float* p1 = g_mAcc + (size_t)sRecv[r1] * 128;
#pragma unroll
        for (int j = 0; j < 16; j++) {
            int c = j * 8 + 2 * tig;
            red2(p0 + c, d[j][0] * g0, d[j][1] * g0);
            red2(p1 + c, d[j][2] * g1, d[j][3] * g1);
        }
    }
    waitW0(); __syncthreads();

    // ---- T3 = Lx0, rotation (0,1,2) ----
    loadW32(a2, g_WF[4], tid);           // T4.hi -> b2
    zero_d(d);
    mma12(d, ah, al, B0, lane);
    __syncthreads();
    loadW32(a0, g_WF[4] + 8192, tid);    // T4.lo -> b0
    mma3(d, ah, B1, lane);
    {   // Lx0 epilogue
#pragma unroll
        for (int kc = 0; kc < 8; kc++)
#pragma unroll
            for (int u = 0; u < 2; u++) {
                int j = 2 * kc + u, c = j * 8 + 2 * tig;
                float2 bb = *(const float2*)(sBias + 256 + c);
                float v0 = fsilu(d[j][0] + bb.x), v1 = fsilu(d[j][1] + bb.y);
                float v2 = fsilu(d[j][2] + bb.x), v3 = fsilu(d[j][3] + bb.y);
                split2(v0, v1, ah[kc][2 * u], al[kc][2 * u]);
                split2(v2, v3, ah[kc][2 * u + 1], al[kc][2 * u + 1]);
            }
    }
    waitW0(); __syncthreads();

    // ---- T4 = Lx1, rotation (2,0,1) ----
    zero_d(d);
    mma12(d, ah, al, B2, lane);
    mma3(d, ah, B0, lane);
    {   // Lx1 epilogue: phi_x dots + shift scatter
        float pa0 = 0.f, pa1 = 0.f, pa2 = 0.f, pb0 = 0.f, pb1 = 0.f, pb2 = 0.f;
#pragma unroll
        for (int kc = 0; kc < 8; kc++)
#pragma unroll
            for (int u = 0; u < 2; u++) {
                int j = 2 * kc + u, c = j * 8 + 2 * tig;
                float2 bb = *(const float2*)(sBias + 384 + c);
                float2 q0 = *(const float2*)(sBias + 1024 + c);
                float2 q1 = *(const float2*)(sBias + 1152 + c);
                float2 q2 = *(const float2*)(sBias + 1280 + c);
                float v0 = fsilu(d[j][0] + bb.x), v1 = fsilu(d[j][1] + bb.y);
                float v2 = fsilu(d[j][2] + bb.x), v3 = fsilu(d[j][3] + bb.y);
                pa0 += v0 * q0.x + v1 * q0.y; pa1 += v0 * q1.x + v1 * q1.y; pa2 += v0 * q2.x + v1 * q2.y;
                pb0 += v2 * q0.x + v3 * q0.y; pb1 += v2 * q1.x + v3 * q1.y; pb2 += v2 * q2.x + v3 * q2.y;
            }
#pragma unroll
        for (int msk = 1; msk <= 2; msk <<= 1) {
            pa0 += __shfl_xor_sync(0xffffffffu, pa0, msk);
            pa1 += __shfl_xor_sync(0xffffffffu, pa1, msk);
            pa2 += __shfl_xor_sync(0xffffffffu, pa2, msk);
            pb0 += __shfl_xor_sync(0xffffffffu, pb0, msk);
            pb1 += __shfl_xor_sync(0xffffffffu, pb1, msk);
            pb2 += __shfl_xor_sync(0xffffffffu, pb2, msk);
        }
        if (tig == 0) {
            float pv0[3] = { pa0, pa1, pa2 }, pv1[3] = { pb0, pb1, pb2 };
            const float* svr0 = sVec + r0 * 16;
            const float* svr1 = sVec + r1 * 16;
            float* d0 = g_vAcc + (size_t)sRecv[r0] * 9;
            float* d1 = g_vAcc + (size_t)sRecv[r1] * 9;
#pragma unroll
            for (int v = 0; v < 3; v++) {
                float sc0 = (pv0[v] + sBias[1408 + v]) * frcp(1.0f + svr0[9 + v]);
                float sc1 = (pv1[v] + sBias[1408 + v]) * frcp(1.0f + svr1[9 + v]);
#pragma unroll
                for (int dd = 0; dd < 3; dd++) {
                    atomicAdd(d0 + v * 3 + dd, sc0 * svr0[v * 3 + dd]);
                    atomicAdd(d1 + v * 3 + dd, sc1 * svr1[v * 3 + dd]);
                }
            }
        }
    }
}

// ======================= node kernel: 64 nodes / 4 warps / 2 blocks per SM =========
extern "C" __global__ void __launch_bounds__(128, 2)
node_kernel(const float* __restrict__ pos, const float* __restrict__ feat,
            const float* __restrict__ b_h0, const float* __restrict__ b_h1,
            const float* __restrict__ b_h2, float* __restrict__ out)
{
    extern __shared__ __align__(16) float sm[];
    const uint32_t sA = smem_u32(sm);
    const int tid = threadIdx.x, lane = tid & 31, warp = tid >> 5;
    const int g = lane >> 2, tig = lane & 3;
    const int r0 = warp * 16 + g, r1 = r0 + 8;
    const int nBase = blockIdx.x * 64;
    const int node0 = nBase + r0, node1 = nBase + r1;
    const bool va = node0 < N_NODES, vb = node1 < N_NODES;
    const uint32_t* B0 = (const uint32_t*)sm;
    const uint32_t* B1 = B0 + 8192;
    const uint32_t* B2 = B0 + 16384;
    const uint32_t a0 = sA, a1 = sA + 32768, a2 = sA + 65536;
    float* sBias = sm + SF_BIAS;

    loadW32(a0, g_WF[5], tid);           // T5.hi
    loadW32(a1, g_WF[5] + 8192, tid);    // T5.lo
    loadW32(a2, g_WF[6], tid);           // T6.hi
    for (int i = tid; i < 128; i += 128) {
        sBias[i] = b_h0[i]; sBias[128 + i] = b_h1[i]; sBias[256 + i] = b_h2[i];
    }
    const float invNN = 1.0f / 19999.0f;
    for (int idx = tid; idx < 64 * 9; idx += 128) {
        const int i = idx / 9, c = idx - i * 9;
        const int n = nBase + i;
        if (n < N_NODES)
            out[(size_t)n * 9 + c] = pos[(size_t)n * 9 + c] + g_vAcc[(size_t)n * 9 + c] * invNN;
    }

    float d[16][4];
    uint32_t ah[8][4], al[8][4];
    const float invSq = rsqrtf(19999.0f);
    {   // m_i * invSq frags
        const float* f0 = g_mAcc + (size_t)(va ? node0 : 0) * 128;
        const float* f1 = g_mAcc + (size_t)(vb ? node1 : 0) * 128;
#pragma unroll
        for (int kc = 0; kc < 8; kc++) gfrag(f0, f1, kc, tig, ah, al, va, vb, invSq);
    }
    waitW1(); __syncthreads();

    // ---- T5 = H0a (m_i), rotation (0,1,2) ----
    zero_d(d);
    mma12(d, ah, al, B0, lane);
    __syncthreads();
    loadW32(a0, g_WF[6] + 8192, tid);    // T6.lo -> b0
    mma3(d, ah, B1, lane);
    {   // feat frags
        const float* f0 = feat + (size_t)(va ? node0 : 0) * 128;
        const float* f1 = feat + (size_t)(vb ? node1 : 0) * 128;
#pragma unroll
        for (int kc = 0; kc < 8; kc++) gfrag(f0, f1, kc, tig, ah, al, va, vb, 1.f);
    }
    waitW0(); __syncthreads();

    // ---- T6 = H0b (feat, accumulate), rotation (2,0,1) ----
    loadW32(a1, g_WF[7], tid);           // T7.hi -> b1
    mma12(d, ah, al, B2, lane);
    __syncthreads();
    loadW32(a2, g_WF[7] + 8192, tid);    // T7.lo -> b2
    mma3(d, ah, B0, lane);
#pragma unroll
    for (int kc = 0; kc < 8; kc++)        // h0 epilogue
#pragma unroll
        for (int u = 0; u < 2; u++) {
            int j = 2 * kc + u, c = j * 8 + 2 * tig;
            float2 bb = *(const float2*)(sBias + c);
            float v0 = fsilu(d[j][0] + bb.x), v1 = fsilu(d[j][1] + bb.y);
            float v2 = fsilu(d[j][2] + bb.x), v3 = fsilu(d[j][3] + bb.y);
            split2(v0, v1, ah[kc][2 * u], al[kc][2 * u]);
            split2(v2, v3, ah[kc][2 * u + 1], al[kc][2 * u + 1]);
        }
    waitW0(); __syncthreads();

    // ---- T7 = H1, rotation (1,2,0) ----
    loadW32(a0, g_WF[8], tid);           // T8.hi -> b0
    zero_d(d);
    mma12(d, ah, al, B1, lane);
    __syncthreads();
    loadW32(a1, g_WF[8] + 8192, tid);    // T8.lo -> b1
    mma3(d, ah, B2, lane);
#pragma unroll
    for (int kc = 0; kc < 8; kc++)        // h1 epilogue
#pragma unroll
        for (int u = 0; u < 2; u++) {
            int j = 2 * kc + u, c = j * 8 + 2 * tig;
            float2 bb = *(const float2*)(sBias + 128 + c);
            float v0 = fsilu(d[j][0] + bb.x), v1 = fsilu(d[j][1] + bb.y);
            float v2 = fsilu(d[j][2] + bb.x), v3 = fsilu(d[j][3] + bb.y);
            split2(v0, v1, ah[kc][2 * u], al[kc][2 * u]);
            split2(v2, v3, ah[kc][2 * u + 1], al[kc][2 * u + 1]);
        }
    waitW0(); __syncthreads();

    // ---- T8 = H2, rotation (0,1,2) ----
    zero_d(d);
    mma12(d, ah, al, B0, lane);
    mma3(d, ah, B1, lane);
    // h2 + residual -> out
#pragma unroll
    for (int j = 0; j < 16; j++) {
        int c = j * 8 + 2 * tig;
        float2 bb = *(const float2*)(sBias + 256 + c);
        if (va) {
            float2 f = __ldg((const float2*)(feat + (size_t)node0 * 128 + c));
            float2 o = make_float2(d[j][0] + bb.x + f.x, d[j][1] + bb.y + f.y);
            *(float2*)(out + VOFF + (size_t)node0 * 128 + c) = o;
        }
        if (vb) {
            float2 f = __ldg((const float2*)(feat + (size_t)node1 * 128 + c));
            float2 o = make_float2(d[j][2] + bb.x + f.x, d[j][3] + bb.y + f.y);
            *(float2*)(out + VOFF + (size_t)node1 * 128 + c) = o;
        }
    }
}

// ======================= prep + zero =======================
__global__ void prep_kernel(const float* __restrict__ w_e0, const float* __restrict__ w_e1,
                            const float* __restrict__ w_x0, const float* __restrict__ w_x1,
                            const float* __restrict__ w_xo,
                            const float* __restrict__ w_h0, const float* __restrict__ w_h1,
                            const float* __restrict__ w_h2)
{
    const int idx = blockIdx.x * blockDim.x + threadIdx.x;
    const int stride = gridDim.x * blockDim.x;
    const float* srcs[9] = { w_e0, w_e0, w_e1, w_x0, w_x1, w_h0, w_h0, w_h1, w_h2 };
    const int koff[9] = { 0, 128, 0, 0, 0, 0, 128, 0, 0 };
    for (int i = idx; i < 9 * 8192; i += stride) {
        const int t = i >> 13, fi = i & 8191;
        const int ri = fi & 1, ln = (fi >> 1) & 31, j = (fi >> 6) & 15, kc = fi >> 10;
        const int tg = ln & 3, gg = ln >> 2;
        const int k = kc * 16 + ri * 8 + tg * 2;
        const int n = j * 8 + gg;
        const float* s = srcs[t];
        const float wa = s[(size_t)(koff[t] + k) * 128 + n];
        const float wb = s[(size_t)(koff[t] + k + 1) * 128 + n];
        const __half ha = __float2half_rn(wa), hb = __float2half_rn(wb);
        const __half la = __float2half_rn(wa - __half2float(ha));
        const __half lb = __float2half_rn(wb - __half2float(hb));
        g_WF[t][fi] = (uint32_t)__half_as_ushort(ha) | ((uint32_t)__half_as_ushort(hb) << 16);
        g_WF[t][8192 + fi] = (uint32_t)__half_as_ushort(la) | ((uint32_t)__half_as_ushort(lb) << 16);
    }
    for (int i = idx; i < 384; i += stride) {
        const int v = i >> 7, k = i & 127;
        g_W0c[i]  = w_e0[(size_t)(256 + v) * 128 + k];
        g_Wout[i] = w_xo[(size_t)k * 3 + v];
    }
}

__global__ void zero_kernel()
{
    const int idx = blockIdx.x * blockDim.x + threadIdx.x;
    const int stride = gridDim.x * blockDim.x;
    for (int i = idx; i < N_NODES * 128; i += stride) g_mAcc[i] = 0.f;
    for (int i = idx; i < N_NODES * 9; i += stride)   g_vAcc[i] = 0.f;
}

// ======================= launch =======================
extern "C" void kernel_launch(void* const* d_in, const int* in_sizes, int n_in,
                              void* d_out, int out_size)
{
    (void)in_sizes; (void)n_in; (void)out_size;
    const float* pos  = (const float*)d_in[0];
    const float* feat = (const float*)d_in[1];
    const int* senders   = (const int*)d_in[2];
    const int* receivers = (const int*)d_in[3];
    const float* w_e0 = (const float*)d_in[4];  const float* b_e0 = (const float*)d_in[5];
    const float* w_e1 = (const float*)d_in[6];  const float* b_e1 = (const float*)d_in[7];
    const float* w_x0 = (const float*)d_in[8];  const float* b_x0 = (const float*)d_in[9];
    const float* w_x1 = (const float*)d_in[10]; const float* b_x1 = (const float*)d_in[11];
    const float* w_xo = (const float*)d_in[12]; const float* b_xo = (const float*)d_in[13];
    const float* w_if = (const float*)d_in[14]; const float* b_if = (const float*)d_in[15];
    const float* w_h0 = (const float*)d_in[16]; const float* b_h0 = (const float*)d_in[17];
    const float* w_h1 = (const float*)d_in[18]; const float* b_h1 = (const float*)d_in[19];
    const float* w_h2 = (const float*)d_in[20]; const float* b_h2 = (const float*)d_in[21];
    float* out = (float*)d_out;

    cudaFuncSetAttribute(edge_kernel, cudaFuncAttributeMaxDynamicSharedMemorySize, SMEM_BYTES);
    cudaFuncSetAttribute(node_kernel, cudaFuncAttributeMaxDynamicSharedMemorySize, SMEM_BYTES);

    prep_kernel<<<128, 256>>>(w_e0, w_e1, w_x0, w_x1, w_xo, w_h0, w_h1, w_h2);
    zero_kernel<<<256, 256>>>();
    edge_kernel<<<E_EDGES / 64, 128, SMEM_BYTES>>>(pos, feat, senders, receivers,
                                                   b_e0, b_e1, b_x0, b_x1, b_xo, w_if, b_if);
    node_kernel<<<(N_NODES + 63) / 64, 128, SMEM_BYTES>>>(pos, feat, b_h0, b_h1, b_h2, out);
}

// round 7
// speedup vs baseline: 5.5319x; 1.7520x over previous
#include <cuda_runtime.h>
#include <cuda_fp16.h>
#include <cstdint>

#define N_NODES 20000
#define E_EDGES 640000
#define VOFF (N_NODES * 9)

// fragment-ordered weight tiles: [tile][hi:0..8191 | lo:8192..16383] u32 (2 fp16 each)
// tiles: 0=L0a 1=L0b 2=L1 3=Lx0 4=Lx1 5=H0a 6=H0b 7=H1 8=H2
__device__ __align__(16) uint32_t g_WF[9][16384];
__device__ float g_W0c[384];    // w_e0 rows 256..258, [v][out]
__device__ float g_Wout[384];   // phi_x_out_w^T [v][k]
__device__ __align__(16) float g_mAcc[N_NODES * 128];
__device__ __align__(16) float g_vAcc[N_NODES * 9];

// edge smem (float units): buf0 u32[8192] | buf1 u32[8192] | bias 1536 | vec 1024 | recv 64
#define EF_BIAS 16384
#define EF_VEC  17920
#define EF_RECV 18944
#define ESM_BYTES (19008 * 4)
// node smem: buf0|buf1|buf2 u32[8192 each] | bias 384
#define NF_BIAS 24576
#define NSM_BYTES (24960 * 4)

// ---------------- fast activations (MUFU ex2/rcp; MUFU pipe idle in tensor era) ----
__device__ __forceinline__ float fsilu(float x) {
    float e; asm("ex2.approx.f32 %0, %1;" : "=f"(e) : "f"(x * -1.44269504f));
    float r; asm("rcp.approx.f32 %0, %1;" : "=f"(r) : "f"(1.0f + e));
    return x * r;
}
__device__ __forceinline__ float fsigmoid(float x) {
    float e; asm("ex2.approx.f32 %0, %1;" : "=f"(e) : "f"(x * -1.44269504f));
    float r; asm("rcp.approx.f32 %0, %1;" : "=f"(r) : "f"(1.0f + e));
    return r;
}
__device__ __forceinline__ float frcp(float d) {
    float r; asm("rcp.approx.f32 %0, %1;" : "=f"(r) : "f"(d));
    return r;
}

// ---------------- frag / mma helpers ----------------
__device__ __forceinline__ uint32_t smem_u32(const void* p) {
    uint32_t a;
    asm("{ .reg .u64 t; cvta.to.shared.u64 t, %1; cvt.u32.u64 %0, t; }" : "=r"(a) : "l"(p));
    return a;
}
__device__ __forceinline__ void split2(float x, float y, uint32_t& hi, uint32_t& lo) {
    __half2 h = __floats2half2_rn(x, y);
    float2 hf = __half22float2(h);
    __half2 l = __floats2half2_rn(x - hf.x, y - hf.y);
    hi = *reinterpret_cast<uint32_t*>(&h);
    lo = *reinterpret_cast<uint32_t*>(&l);
}
__device__ __forceinline__ void mma16816(float* d, const uint32_t* a, uint32_t b0, uint32_t b1) {
    asm volatile("mma.sync.aligned.m16n8k16.row.col.f32.f16.f16.f32 "
                 "{%0,%1,%2,%3}, {%4,%5,%6,%7}, {%8,%9}, {%0,%1,%2,%3};"
                 : "+f"(d[0]), "+f"(d[1]), "+f"(d[2]), "+f"(d[3])
                 : "r"(a[0]), "r"(a[1]), "r"(a[2]), "r"(a[3]), "r"(b0), "r"(b1));
}
// 2-pass (ah*Whi + al*Whi) over a 32KB hi buffer
__device__ __forceinline__ void mma12(float (&d)[16][4], const uint32_t (&ah)[8][4],
                                      const uint32_t (&al)[8][4], const uint32_t* swHi, int lane) {
#pragma unroll
    for (int kc = 0; kc < 8; kc++)
#pragma unroll
        for (int j = 0; j < 16; j++) {
            uint2 b = *(const uint2*)&swHi[((kc * 16 + j) * 32 + lane) * 2];
            mma16816(d[j], ah[kc], b.x, b.y);
            mma16816(d[j], al[kc], b.x, b.y);
        }
}
// pass 3 (ah*Wlo) over a 32KB lo buffer (node kernel only)
__device__ __forceinline__ void mma3(float (&d)[16][4], const uint32_t (&ah)[8][4],
                                     const uint32_t* swLo, int lane) {
#pragma unroll
    for (int kc = 0; kc < 8; kc++)
#pragma unroll
        for (int j = 0; j < 16; j++) {
            uint2 b = *(const uint2*)&swLo[((kc * 16 + j) * 32 + lane) * 2];
            mma16816(d[j], ah[kc], b.x, b.y);
        }
}
__device__ __forceinline__ void zero_d(float (&d)[16][4]) {
#pragma unroll
    for (int j = 0; j < 16; j++)
#pragma unroll
        for (int q = 0; q < 4; q++) d[j][q] = 0.f;
}
// load one 32KB half-tile (2048 x 16B), own commit group
__device__ __forceinline__ void loadW32(uint32_t sAddr, const uint32_t* g, int tid) {
#pragma unroll 1
    for (int i = tid; i < 2048; i += 128)
        asm volatile("cp.async.cg.shared.global [%0], [%1], 16;"
                     :: "r"(sAddr + i * 16), "l"(g + i * 4));
    asm volatile("cp.async.commit_group;" ::: "memory");
}
__device__ __forceinline__ void waitW0() { asm volatile("cp.async.wait_group 0;" ::: "memory"); }
__device__ __forceinline__ void waitW1() { asm volatile("cp.async.wait_group 1;" ::: "memory"); }
__device__ __forceinline__ void red2(float* p, float x, float y) {
    asm volatile("red.global.add.v2.f32 [%0], {%1,%2};" :: "l"(p), "f"(x), "f"(y) : "memory");
}
// gather one K=16 chunk (2 rows) of fp32 features into A frags
__device__ __forceinline__ void gfrag(const float* f0, const float* f1, int kc, int tig,
                                      uint32_t (&ah)[8][4], uint32_t (&al)[8][4],
                                      bool v0, bool v1, float scale) {
    float2 z = make_float2(0.f, 0.f);
    float2 x0 = v0 ? __ldg((const float2*)(f0 + kc * 16 + 2 * tig)) : z;
    float2 x1 = v1 ? __ldg((const float2*)(f1 + kc * 16 + 2 * tig)) : z;
    float2 y0 = v0 ? __ldg((const float2*)(f0 + kc * 16 + 8 + 2 * tig)) : z;
    float2 y1 = v1 ? __ldg((const float2*)(f1 + kc * 16 + 8 + 2 * tig)) : z;
    split2(x0.x * scale, x0.y * scale, ah[kc][0], al[kc][0]);
    split2(x1.x * scale, x1.y * scale, ah[kc][1], al[kc][1]);
    split2(y0.x * scale, y0.y * scale, ah[kc][2], al[kc][2]);
    split2(y1.x * scale, y1.y * scale, ah[kc][3], al[kc][3]);
}

// ======== edge kernel: 64 edges / 4 warps, 2-pass weights, 3 blocks per SM ========
extern "C" __global__ void __launch_bounds__(128, 3)
edge_kernel(const float* __restrict__ pos, const float* __restrict__ feat,
            const int* __restrict__ senders, const int* __restrict__ receivers,
            const float* __restrict__ b_e0, const float* __restrict__ b_e1,
            const float* __restrict__ b_x0, const float* __restrict__ b_x1,
            const float* __restrict__ b_xo, const float* __restrict__ w_inf,
            const float* __restrict__ b_inf)
{
    extern __shared__ __align__(16) float sm[];
    const uint32_t sA = smem_u32(sm);
    const int tid = threadIdx.x, lane = tid & 31, warp = tid >> 5;
    const int g = lane >> 2, tig = lane & 3;
    const int r0 = warp * 16 + g, r1 = r0 + 8;      // rows 0..63
    const int eBase = blockIdx.x * 64;
    const uint32_t* B0 = (const uint32_t*)sm;
    const uint32_t* B1 = B0 + 8192;
    const uint32_t a0 = sA, a1 = sA + 32768;
    float* sBias = sm + EF_BIAS;
    float* sVec  = sm + EF_VEC;
    int*   sRecv = (int*)(sm + EF_RECV);

    loadW32(a0, g_WF[0], tid);           // T0 = L0a.hi
    loadW32(a1, g_WF[1], tid);           // T1 = L0b.hi

    for (int i = tid; i < 128; i += 128) {
        sBias[i] = b_e0[i]; sBias[128 + i] = b_e1[i];
        sBias[256 + i] = b_x0[i]; sBias[384 + i] = b_x1[i];
        sBias[512 + i] = w_inf[i];
    }
    for (int i = tid; i < 384; i += 128) { sBias[640 + i] = g_W0c[i]; sBias[1024 + i] = g_Wout[i]; }
    if (tid < 3) sBias[1408 + tid] = b_xo[tid];
    if (tid == 3) sBias[1411] = b_inf[0];

    if (tid < 64) {                      // per-edge geometry
        const int e = eBase + tid;
        const int s = senders[e], rc = receivers[e];
        sRecv[tid] = rc;
        const float* ps = pos + (size_t)s * 9;
        const float* pr = pos + (size_t)rc * 9;
        float* sv = sVec + tid * 16;
#pragma unroll
        for (int v = 0; v < 3; v++) {
            float n2 = 0.f;
#pragma unroll
            for (int dd = 0; dd < 3; dd++) {
                float dv = pr[v * 3 + dd] - ps[v * 3 + dd];
                sv[v * 3 + dd] = dv; n2 += dv * dv;
            }
            sv[9 + v] = (n2 > 0.f) ? sqrtf(n2) : 0.f;
            sv[12 + v] = n2;
        }
    }

    float d[16][4];
    uint32_t ah[8][4], al[8][4];
    const int e0 = eBase + r0, e1 = eBase + r1;

    {   // featS A-frags
        const float* f0 = feat + (size_t)senders[e0] * 128;
        const float* f1 = feat + (size_t)senders[e1] * 128;
#pragma unroll
        for (int kc = 0; kc < 8; kc++) gfrag(f0, f1, kc, tig, ah, al, true, true, 1.f);
    }
    waitW1(); __syncthreads();           // T0 ready (T1 may be in flight)

    // ---- L0a (featS x W0[0:128]) on b0 ----
    zero_d(d);
    mma12(d, ah, al, B0, lane);
    __syncthreads();
    loadW32(a0, g_WF[2], tid);           // T2 = L1.hi -> b0
    {   // featR A-frags
        const float* f0 = feat + (size_t)receivers[e0] * 128;
        const float* f1 = feat + (size_t)receivers[e1] * 128;
#pragma unroll
        for (int kc = 0; kc < 8; kc++) gfrag(f0, f1, kc, tig, ah, al, true, true, 1.f);
    }
    waitW1(); __syncthreads();           // T1 ready (T2 in flight)

    // ---- L0b (featR, accumulate) on b1 ----
    mma12(d, ah, al, B1, lane);
    __syncthreads();
    loadW32(a1, g_WF[3], tid);           // T3 = Lx0.hi -> b1
    {   // L0 epilogue: + bias + sq·w0c, silu -> frags
        const float* svr0 = sVec + r0 * 16;
        const float* svr1 = sVec + r1 * 16;
        float sa0 = svr0[12], sa1 = svr0[13], sa2 = svr0[14];
        float sb0 = svr1[12], sb1 = svr1[13], sb2 = svr1[14];
#pragma unroll
        for (int kc = 0; kc < 8; kc++)
#pragma unroll
            for (int u = 0; u < 2; u++) {
                int j = 2 * kc + u, c = j * 8 + 2 * tig;
                float2 bb = *(const float2*)(sBias + c);
                float2 w0 = *(const float2*)(sBias + 640 + c);
                float2 w1 = *(const float2*)(sBias + 768 + c);
                float2 w2 = *(const float2*)(sBias + 896 + c);
                float v0 = fsilu(d[j][0] + bb.x + sa0 * w0.x + sa1 * w1.x + sa2 * w2.x);
                float v1 = fsilu(d[j][1] + bb.y + sa0 * w0.y + sa1 * w1.y + sa2 * w2.y);
                float v2 = fsilu(d[j][2] + bb.x + sb0 * w0.x + sb1 * w1.x + sb2 * w2.x);
                float v3 = fsilu(d[j][3] + bb.y + sb0 * w0.y + sb1 * w1.y + sb2 * w2.y);
                split2(v0, v1, ah[kc][2 * u], al[kc][2 * u]);
                split2(v2, v3, ah[kc][2 * u + 1], al[kc][2 * u + 1]);
            }
    }
    waitW1(); __syncthreads();           // T2 ready (T3 in flight)

    // ---- L1 -> m_ij on b0 ----
    zero_d(d);
    mma12(d, ah, al, B0, lane);
    __syncthreads();
    loadW32(a0, g_WF[4], tid);           // T4 = Lx1.hi -> b0
    {   // L1 epilogue: silu, gate dot, frags, m-scatter
        float s0 = 0.f, s1 = 0.f;
#pragma unroll
        for (int kc = 0; kc < 8; kc++)
#pragma unroll
            for (int u = 0; u < 2; u++) {
                int j = 2 * kc + u, c = j * 8 + 2 * tig;
                float2 bb = *(const float2*)(sBias + 128 + c);
                float2 wf = *(const float2*)(sBias + 512 + c);
                float v0 = fsilu(d[j][0] + bb.x), v1 = fsilu(d[j][1] + bb.y);
                float v2 = fsilu(d[j][2] + bb.x), v3 = fsilu(d[j][3] + bb.y);
                s0 += v0 * wf.x + v1 * wf.y;
                s1 += v2 * wf.x + v3 * wf.y;
                d[j][0] = v0; d[j][1] = v1; d[j][2] = v2; d[j][3] = v3;
                split2(v0, v1, ah[kc][2 * u], al[kc][2 * u]);
                split2(v2, v3, ah[kc][2 * u + 1], al[kc][2 * u + 1]);
            }
        s0 += __shfl_xor_sync(0xffffffffu, s0, 1); s0 += __shfl_xor_sync(0xffffffffu, s0, 2);
        s1 += __shfl_xor_sync(0xffffffffu, s1, 1); s1 += __shfl_xor_sync(0xffffffffu, s1, 2);
        const float bi = sBias[1411];
        const float g0 = fsigmoid(s0 + bi), g1 = fsigmoid(s1 + bi);
        float* p0 = g_mAcc + (size_t)sRecv[r0] * 128;
        float* p1 = g_mAcc + (size_t)sRecv[r1] * 128;
#pragma unroll
        for (int j = 0; j < 16; j++) {
            int c = j * 8 + 2 * tig;
            red2(p0 + c, d[j][0] * g0, d[j][1] * g0);
            red2(p1 + c, d[j][2] * g1, d[j][3] * g1);
        }
    }
    waitW1(); __syncthreads();           // T3 ready (T4 in flight)

    // ---- Lx0 on b1 ----
    zero_d(d);
    mma12(d, ah, al, B1, lane);
    {   // Lx0 epilogue
#pragma unroll
        for (int kc = 0; kc < 8; kc++)
#pragma unroll
            for (int u = 0; u < 2; u++) {
                int j = 2 * kc + u, c = j * 8 + 2 * tig;
                float2 bb = *(const float2*)(sBias + 256 + c);
                float v0 = fsilu(d[j][0] + bb.x), v1 = fsilu(d[j][1] + bb.y);
                float v2 = fsilu(d[j][2] + bb.x), v3 = fsilu(d[j][3] + bb.y);
                split2(v0, v1, ah[kc][2 * u], al[kc][2 * u]);
                split2(v2, v3, ah[kc][2 * u + 1], al[kc][2 * u + 1]);
            }
    }
    waitW0(); __syncthreads();           // T4 ready

    // ---- Lx1 on b0 ----
    zero_d(d);
    mma12(d, ah, al, B0, lane);
    {   // Lx1 epilogue: phi_x dots + shift scatter
        float pa0 = 0.f, pa1 = 0.f, pa2 = 0.f, pb0 = 0.f, pb1 = 0.f, pb2 = 0.f;
#pragma unroll
        for (int kc = 0; kc < 8; kc++)
#pragma unroll
            for (int u = 0; u < 2; u++) {
                int j = 2 * kc + u, c = j * 8 + 2 * tig;
                float2 bb = *(const float2*)(sBias + 384 + c);
                float2 q0 = *(const float2*)(sBias + 1024 + c);
                float2 q1 = *(const float2*)(sBias + 1152 + c);
                float2 q2 = *(const float2*)(sBias + 1280 + c);
                float v0 = fsilu(d[j][0] + bb.x), v1 = fsilu(d[j][1] + bb.y);
                float v2 = fsilu(d[j][2] + bb.x), v3 = fsilu(d[j][3] + bb.y);
                pa0 += v0 * q0.x + v1 * q0.y; pa1 += v0 * q1.x + v1 * q1.y; pa2 += v0 * q2.x + v1 * q2.y;
                pb0 += v2 * q0.x + v3 * q0.y; pb1 += v2 * q1.x + v3 * q1.y; pb2 += v2 * q2.x + v3 * q2.y;
            }
#pragma unroll
        for (int msk = 1; msk <= 2; msk <<= 1) {
            pa0 += __shfl_xor_sync(0xffffffffu, pa0, msk);
            pa1 += __shfl_xor_sync(0xffffffffu, pa1, msk);
            pa2 += __shfl_xor_sync(0xffffffffu, pa2, msk);
            pb0 += __shfl_xor_sync(0xffffffffu, pb0, msk);
            pb1 += __shfl_xor_sync(0xffffffffu, pb1, msk);
            pb2 += __shfl_xor_sync(0xffffffffu, pb2, msk);
        }
        if (tig == 0) {
            float pv0[3] = { pa0, pa1, pa2 }, pv1[3] = { pb0, pb1, pb2 };
            const float* svr0 = sVec + r0 * 16;
            const float* svr1 = sVec + r1 * 16;
            float* d0 = g_vAcc + (size_t)sRecv[r0] * 9;
            float* d1 = g_vAcc + (size_t)sRecv[r1] * 9;
#pragma unroll
            for (int v = 0; v < 3; v++) {
                float sc0 = (pv0[v] + sBias[1408 + v]) * frcp(1.0f + svr0[9 + v]);
                float sc1 = (pv1[v] + sBias[1408 + v]) * frcp(1.0f + svr1[9 + v]);
#pragma unroll
                for (int dd = 0; dd < 3; dd++) {
                    atomicAdd(d0 + v * 3 + dd, sc0 * svr0[v * 3 + dd]);
                    atomicAdd(d1 + v * 3 + dd, sc1 * svr1[v * 3 + dd]);
                }
            }
        }
    }
}

// ======== node kernel: 64 nodes / 4 warps, full 3-pass, 2 blocks per SM ========
extern "C" __global__ void __launch_bounds__(128, 2)
node_kernel(const float* __restrict__ pos, const float* __restrict__ feat,
            const float* __restrict__ b_h0, const float* __restrict__ b_h1,
            const float* __restrict__ b_h2, float* __restrict__ out)
{
    extern __shared__ __align__(16) float sm[];
    const uint32_t sA = smem_u32(sm);
    const int tid = threadIdx.x, lane = tid & 31, warp = tid >> 5;
    const int g = lane >> 2, tig = lane & 3;
    const int r0 = warp * 16 + g, r1 = r0 + 8;
    const int nBase = blockIdx.x * 64;
    const int node0 = nBase + r0, node1 = nBase + r1;
    const bool va = node0 < N_NODES, vb = node1 < N_NODES;
    const uint32_t* B0 = (const uint32_t*)sm;
    const uint32_t* B1 = B0 + 8192;
    const uint32_t* B2 = B0 + 16384;
    const uint32_t a0 = sA, a1 = sA + 32768, a2 = sA + 65536;
    float* sBias = sm + NF_BIAS;

    loadW32(a0, g_WF[5], tid);           // T5.hi
    loadW32(a1, g_WF[5] + 8192, tid);    // T5.lo
    loadW32(a2, g_WF[6], tid);           // T6.hi
    for (int i = tid; i < 128; i += 128) {
        sBias[i] = b_h0[i]; sBias[128 + i] = b_h1[i]; sBias[256 + i] = b_h2[i];
    }
    const float invNN = 1.0f / 19999.0f;
    for (int idx = tid; idx < 64 * 9; idx += 128) {
        const int i = idx / 9, c = idx - i * 9;
        const int n = nBase + i;
        if (n < N_NODES)
            out[(size_t)n * 9 + c] = pos[(size_t)n * 9 + c] + g_vAcc[(size_t)n * 9 + c] * invNN;
    }

    float d[16][4];
    uint32_t ah[8][4], al[8][4];
    const float invSq = rsqrtf(19999.0f);
    {   // m_i * invSq frags
        const float* f0 = g_mAcc + (size_t)(va ? node0 : 0) * 128;
        const float* f1 = g_mAcc + (size_t)(vb ? node1 : 0) * 128;
#pragma unroll
        for (int kc = 0; kc < 8; kc++) gfrag(f0, f1, kc, tig, ah, al, va, vb, invSq);
    }
    waitW1(); __syncthreads();

    // ---- T5 = H0a (m_i), rotation (0,1,2) ----
    zero_d(d);
    mma12(d, ah, al, B0, lane);
    __syncthreads();
    loadW32(a0, g_WF[6] + 8192, tid);    // T6.lo -> b0
    mma3(d, ah, B1, lane);
    {   // feat frags
        const float* f0 = feat + (size_t)(va ? node0 : 0) * 128;
        const float* f1 = feat + (size_t)(vb ? node1 : 0) * 128;
#pragma unroll
        for (int kc = 0; kc < 8; kc++) gfrag(f0, f1, kc, tig, ah, al, va, vb, 1.f);
    }
    waitW0(); __syncthreads();

    // ---- T6 = H0b (feat, accumulate), rotation (2,0,1) ----
    loadW32(a1, g_WF[7], tid);           // T7.hi -> b1
    mma12(d, ah, al, B2, lane);
    __syncthreads();
    loadW32(a2, g_WF[7] + 8192, tid);    // T7.lo -> b2
    mma3(d, ah, B0, lane);
#pragma unroll
    for (int kc = 0; kc < 8; kc++)        // h0 epilogue
#pragma unroll
        for (int u = 0; u < 2; u++) {
            int j = 2 * kc + u, c = j * 8 + 2 * tig;
            float2 bb = *(const float2*)(sBias + c);
            float v0 = fsilu(d[j][0] + bb.x), v1 = fsilu(d[j][1] + bb.y);
            float v2 = fsilu(d[j][2] + bb.x), v3 = fsilu(d[j][3] + bb.y);
            split2(v0, v1, ah[kc][2 * u], al[kc][2 * u]);
            split2(v2, v3, ah[kc][2 * u + 1], al[kc][2 * u + 1]);
        }
    waitW0(); __syncthreads();

    // ---- T7 = H1, rotation (1,2,0) ----
    loadW32(a0, g_WF[8], tid);           // T8.hi -> b0
    zero_d(d);
    mma12(d, ah, al, B1, lane);
    __syncthreads();
    loadW32(a1, g_WF[8] + 8192, tid);    // T8.lo -> b1
    mma3(d, ah, B2, lane);
#pragma unroll
    for (int kc = 0; kc < 8; kc++)        // h1 epilogue
#pragma unroll
        for (int u = 0; u < 2; u++) {
            int j = 2 * kc + u, c = j * 8 + 2 * tig;
            float2 bb = *(const float2*)(sBias + 128 + c);
            float v0 = fsilu(d[j][0] + bb.x), v1 = fsilu(d[j][1] + bb.y);
            float v2 = fsilu(d[j][2] + bb.x), v3 = fsilu(d[j][3] + bb.y);
            split2(v0, v1, ah[kc][2 * u], al[kc][2 * u]);
            split2(v2, v3, ah[kc][2 * u + 1], al[kc][2 * u + 1]);
        }
    waitW0(); __syncthreads();

    // ---- T8 = H2, rotation (0,1,2) ----
    zero_d(d);
    mma12(d, ah, al, B0, lane);
    mma3(d, ah, B1, lane);
    // h2 + residual -> out
#pragma unroll
    for (int j = 0; j < 16; j++) {
        int c = j * 8 + 2 * tig;
        float2 bb = *(const float2*)(sBias + 256 + c);
        if (va) {
            float2 f = __ldg((const float2*)(feat + (size_t)node0 * 128 + c));
            float2 o = make_float2(d[j][0] + bb.x + f.x, d[j][1] + bb.y + f.y);
            *(float2*)(out + VOFF + (size_t)node0 * 128 + c) = o;
        }
        if (vb) {
            float2 f = __ldg((const float2*)(feat + (size_t)node1 * 128 + c));
            float2 o = make_float2(d[j][2] + bb.x + f.x, d[j][3] + bb.y + f.y);
            *(float2*)(out + VOFF + (size_t)node1 * 128 + c) = o;
        }
    }
}

// ======================= prep + zero =======================
__global__ void prep_kernel(const float* __restrict__ w_e0, const float* __restrict__ w_e1,
                            const float* __restrict__ w_x0, const float* __restrict__ w_x1,
                            const float* __restrict__ w_xo,
                            const float* __restrict__ w_h0, const float* __restrict__ w_h1,
                            const float* __restrict__ w_h2)
{
    const int idx = blockIdx.x * blockDim.x + threadIdx.x;
    const int stride = gridDim.x * blockDim.x;
    const float* srcs[9] = { w_e0, w_e0, w_e1, w_x0, w_x1, w_h0, w_h0, w_h1, w_h2 };
    const int koff[9] = { 0, 128, 0, 0, 0, 0, 128, 0, 0 };
    for (int i = idx; i < 9 * 8192; i += stride) {
        const int t = i >> 13, fi = i & 8191;
        const int ri = fi & 1, ln = (fi >> 1) & 31, j = (fi >> 6) & 15, kc = fi >> 10;
        const int tg = ln & 3, gg = ln >> 2;
        const int k = kc * 16 + ri * 8 + tg * 2;
        const int n = j * 8 + gg;
        const float* s = srcs[t];
        const float wa = s[(size_t)(koff[t] + k) * 128 + n];
        const float wb = s[(size_t)(koff[t] + k + 1) * 128 + n];
        const __half ha = __float2half_rn(wa), hb = __float2half_rn(wb);
        const __half la = __float2half_rn(wa - __half2float(ha));
        const __half lb = __float2half_rn(wb - __half2float(hb));
        g_WF[t][fi] = (uint32_t)__half_as_ushort(ha) | ((uint32_t)__half_as_ushort(hb) << 16);
        g_WF[t][8192 + fi] = (uint32_t)__half_as_ushort(la) | ((uint32_t)__half_as_ushort(lb) << 16);
    }
    for (int i = idx; i < 384; i += stride) {
        const int v = i >> 7, k = i & 127;
        g_W0c[i]  = w_e0[(size_t)(256 + v) * 128 + k];
        g_Wout[i] = w_xo[(size_t)k * 3 + v];
    }
}

__global__ void zero_kernel()
{
    const int idx = blockIdx.x * blockDim.x + threadIdx.x;
    const int stride = gridDim.x * blockDim.x;
    for (int i = idx; i < N_NODES * 128; i += stride) g_mAcc[i] = 0.f;
    for (int i = idx; i < N_NODES * 9; i += stride)   g_vAcc[i] = 0.f;
}

// ======================= launch =======================
extern "C" void kernel_launch(void* const* d_in, const int* in_sizes, int n_in,
                              void* d_out, int out_size)
{
    (void)in_sizes; (void)n_in; (void)out_size;
    const float* pos  = (const float*)d_in[0];
    const float* feat = (const float*)d_in[1];
    const int* senders   = (const int*)d_in[2];
    const int* receivers = (const int*)d_in[3];
    const float* w_e0 = (const float*)d_in[4];  const float* b_e0 = (const float*)d_in[5];
    const float* w_e1 = (const float*)d_in[6];  const float* b_e1 = (const float*)d_in[7];
    const float* w_x0 = (const float*)d_in[8];  const float* b_x0 = (const float*)d_in[9];
    const float* w_x1 = (const float*)d_in[10]; const float* b_x1 = (const float*)d_in[11];
    const float* w_xo = (const float*)d_in[12]; const float* b_xo = (const float*)d_in[13];
    const float* w_if = (const float*)d_in[14]; const float* b_if = (const float*)d_in[15];
    const float* w_h0 = (const float*)d_in[16]; const float* b_h0 = (const float*)d_in[17];
    const float* w_h1 = (const float*)d_in[18]; const float* b_h1 = (const float*)d_in[19];
    const float* w_h2 = (const float*)d_in[20]; const float* b_h2 = (const float*)d_in[21];
    float* out = (float*)d_out;

    cudaFuncSetAttribute(edge_kernel, cudaFuncAttributeMaxDynamicSharedMemorySize, ESM_BYTES);
    cudaFuncSetAttribute(node_kernel, cudaFuncAttributeMaxDynamicSharedMemorySize, NSM_BYTES);

    prep_kernel<<<128, 256>>>(w_e0, w_e1, w_x0, w_x1, w_xo, w_h0, w_h1, w_h2);
    zero_kernel<<<256, 256>>>();
    edge_kernel<<<E_EDGES / 64, 128, ESM_BYTES>>>(pos, feat, senders, receivers,
                                                  b_e0, b_e1, b_x0, b_x1, b_xo, w_if, b_if);
    node_kernel<<<(N_NODES + 63) / 64, 128, NSM_BYTES>>>(pos, feat, b_h0, b_h1, b_h2, out);
}

// round 8
// speedup vs baseline: 6.7160x; 1.2141x over previous
#include <cuda_runtime.h>
#include <cuda_fp16.h>
#include <cstdint>

#define N_NODES 20000
#define E_EDGES 640000
#define VOFF (N_NODES * 9)

// fragment-ordered weight tiles: [tile][hi:0..8191 | lo:8192..16383] u32 (2 fp16 each)
// tiles: 0=L0a 1=L0b 2=L1 3=Lx0 4=Lx1 5=H0a 6=H0b 7=H1 8=H2
__device__ __align__(16) uint32_t g_WF[9][16384];
__device__ float g_W0c[384];    // w_e0 rows 256..258, [v][out]
__device__ float g_Wout[384];   // phi_x_out_w^T [v][k]
__device__ __align__(16) float g_mAcc[N_NODES * 128];
__device__ __align__(16) float g_vAcc[N_NODES * 9];

// edge smem (float units): buf0 u32[8192] | buf1 u32[8192] | bias 1536 | vec 1024 | recv 64
#define EF_BIAS 16384
#define EF_VEC  17920
#define EF_RECV 18944
#define ESM_BYTES (19008 * 4)
// node smem: buf0|buf1|buf2 u32[8192 each] | bias 384
#define NF_BIAS 24576
#define NSM_BYTES (24960 * 4)

// ---------------- fast activations (MUFU ex2/rcp) ----------------
__device__ __forceinline__ float fsilu(float x) {
    float e; asm("ex2.approx.f32 %0, %1;" : "=f"(e) : "f"(x * -1.44269504f));
    float r; asm("rcp.approx.f32 %0, %1;" : "=f"(r) : "f"(1.0f + e));
    return x * r;
}
__device__ __forceinline__ float fsigmoid(float x) {
    float e; asm("ex2.approx.f32 %0, %1;" : "=f"(e) : "f"(x * -1.44269504f));
    float r; asm("rcp.approx.f32 %0, %1;" : "=f"(r) : "f"(1.0f + e));
    return r;
}
__device__ __forceinline__ float frcp(float d) {
    float r; asm("rcp.approx.f32 %0, %1;" : "=f"(r) : "f"(d));
    return r;
}

// ---------------- frag / mma helpers ----------------
__device__ __forceinline__ uint32_t smem_u32(const void* p) {
    uint32_t a;
    asm("{ .reg .u64 t; cvta.to.shared.u64 t, %1; cvt.u32.u64 %0, t; }" : "=r"(a) : "l"(p));
    return a;
}
__device__ __forceinline__ uint32_t pack2(float x, float y) {
    __half2 h = __floats2half2_rn(x, y);
    return *reinterpret_cast<uint32_t*>(&h);
}
__device__ __forceinline__ void split2(float x, float y, uint32_t& hi, uint32_t& lo) {
    __half2 h = __floats2half2_rn(x, y);
    float2 hf = __half22float2(h);
    __half2 l = __floats2half2_rn(x - hf.x, y - hf.y);
    hi = *reinterpret_cast<uint32_t*>(&h);
    lo = *reinterpret_cast<uint32_t*>(&l);
}
__device__ __forceinline__ void mma16816(float* d, const uint32_t* a, uint32_t b0, uint32_t b1) {
    asm volatile("mma.sync.aligned.m16n8k16.row.col.f32.f16.f16.f32 "
                 "{%0,%1,%2,%3}, {%4,%5,%6,%7}, {%8,%9}, {%0,%1,%2,%3};"
                 : "+f"(d[0]), "+f"(d[1]), "+f"(d[2]), "+f"(d[3])
                 : "r"(a[0]), "r"(a[1]), "r"(a[2]), "r"(a[3]), "r"(b0), "r"(b1));
}
// single pass (a*Whi) over a 32KB hi buffer — edge kernel
__device__ __forceinline__ void mma1(float (&d)[16][4], const uint32_t (&ah)[8][4],
                                     const uint32_t* swHi, int lane) {
#pragma unroll
    for (int kc = 0; kc < 8; kc++)
#pragma unroll
        for (int j = 0; j < 16; j++) {
            uint2 b = *(const uint2*)&swHi[((kc * 16 + j) * 32 + lane) * 2];
            mma16816(d[j], ah[kc], b.x, b.y);
        }
}
// 2-pass (ah*Whi + al*Whi) — node kernel
__device__ __forceinline__ void mma12(float (&d)[16][4], const uint32_t (&ah)[8][4],
                                      const uint32_t (&al)[8][4], const uint32_t* swHi, int lane) {
#pragma unroll
    for (int kc = 0; kc < 8; kc++)
#pragma unroll
        for (int j = 0; j < 16; j++) {
            uint2 b = *(const uint2*)&swHi[((kc * 16 + j) * 32 + lane) * 2];
            mma16816(d[j], ah[kc], b.x, b.y);
            mma16816(d[j], al[kc], b.x, b.y);
        }
}
// pass 3 (ah*Wlo) — node kernel
__device__ __forceinline__ void mma3(float (&d)[16][4], const uint32_t (&ah)[8][4],
                                     const uint32_t* swLo, int lane) {
#pragma unroll
    for (int kc = 0; kc < 8; kc++)
#pragma unroll
        for (int j = 0; j < 16; j++) {
            uint2 b = *(const uint2*)&swLo[((kc * 16 + j) * 32 + lane) * 2];
            mma16816(d[j], ah[kc], b.x, b.y);
        }
}
__device__ __forceinline__ void zero_d(float (&d)[16][4]) {
#pragma unroll
    for (int j = 0; j < 16; j++)
#pragma unroll
        for (int q = 0; q < 4; q++) d[j][q] = 0.f;
}
// load one 32KB half-tile (2048 x 16B), own commit group
__device__ __forceinline__ void loadW32(uint32_t sAddr, const uint32_t* g, int tid) {
#pragma unroll 1
    for (int i = tid; i < 2048; i += 128)
        asm volatile("cp.async.cg.shared.global [%0], [%1], 16;"
                     :: "r"(sAddr + i * 16), "l"(g + i * 4));
    asm volatile("cp.async.commit_group;" ::: "memory");
}
__device__ __forceinline__ void waitW0() { asm volatile("cp.async.wait_group 0;" ::: "memory"); }
__device__ __forceinline__ void waitW1() { asm volatile("cp.async.wait_group 1;" ::: "memory"); }
__device__ __forceinline__ void red2(float* p, float x, float y) {
    asm volatile("red.global.add.v2.f32 [%0], {%1,%2};" :: "l"(p), "f"(x), "f"(y) : "memory");
}
// gather one K=16 chunk of fp32 features into fp16 A frags (hi only)
__device__ __forceinline__ void gfrag1(const float* f0, const float* f1, int kc, int tig,
                                       uint32_t (&ah)[8][4]) {
    float2 x0 = __ldg((const float2*)(f0 + kc * 16 + 2 * tig));
    float2 x1 = __ldg((const float2*)(f1 + kc * 16 + 2 * tig));
    float2 y0 = __ldg((const float2*)(f0 + kc * 16 + 8 + 2 * tig));
    float2 y1 = __ldg((const float2*)(f1 + kc * 16 + 8 + 2 * tig));
    ah[kc][0] = pack2(x0.x, x0.y);
    ah[kc][1] = pack2(x1.x, x1.y);
    ah[kc][2] = pack2(y0.x, y0.y);
    ah[kc][3] = pack2(y1.x, y1.y);
}
// hi/lo gather for node kernel
__device__ __forceinline__ void gfrag(const float* f0, const float* f1, int kc, int tig,
                                      uint32_t (&ah)[8][4], uint32_t (&al)[8][4],
                                      bool v0, bool v1, float scale) {
    float2 z = make_float2(0.f, 0.f);
    float2 x0 = v0 ? __ldg((const float2*)(f0 + kc * 16 + 2 * tig)) : z;
    float2 x1 = v1 ? __ldg((const float2*)(f1 + kc * 16 + 2 * tig)) : z;
    float2 y0 = v0 ? __ldg((const float2*)(f0 + kc * 16 + 8 + 2 * tig)) : z;
    float2 y1 = v1 ? __ldg((const float2*)(f1 + kc * 16 + 8 + 2 * tig)) : z;
    split2(x0.x * scale, x0.y * scale, ah[kc][0], al[kc][0]);
    split2(x1.x * scale, x1.y * scale, ah[kc][1], al[kc][1]);
    split2(y0.x * scale, y0.y * scale, ah[kc][2], al[kc][2]);
    split2(y1.x * scale, y1.y * scale, ah[kc][3], al[kc][3]);
}

// ======== edge kernel: 64 edges / 4 warps, 1-pass fp16, 3 blocks per SM ========
extern "C" __global__ void __launch_bounds__(128, 3)
edge_kernel(const float* __restrict__ pos, const float* __restrict__ feat,
            const int* __restrict__ senders, const int* __restrict__ receivers,
            const float* __restrict__ b_e0, const float* __restrict__ b_e1,
            const float* __restrict__ b_x0, const float* __restrict__ b_x1,
            const float* __restrict__ b_xo, const float* __restrict__ w_inf,
            const float* __restrict__ b_inf)
{
    extern __shared__ __align__(16) float sm[];
    const uint32_t sA = smem_u32(sm);
    const int tid = threadIdx.x, lane = tid & 31, warp = tid >> 5;
    const int g = lane >> 2, tig = lane & 3;
    const int r0 = warp * 16 + g, r1 = r0 + 8;      // rows 0..63
    const int eBase = blockIdx.x * 64;
    const uint32_t* B0 = (const uint32_t*)sm;
    const uint32_t* B1 = B0 + 8192;
    const uint32_t a0 = sA, a1 = sA + 32768;
    float* sBias = sm + EF_BIAS;
    float* sVec  = sm + EF_VEC;
    int*   sRecv = (int*)(sm + EF_RECV);

    loadW32(a0, g_WF[0], tid);           // T0 = L0a.hi
    loadW32(a1, g_WF[1], tid);           // T1 = L0b.hi

    for (int i = tid; i < 128; i += 128) {
        sBias[i] = b_e0[i]; sBias[128 + i] = b_e1[i];
        sBias[256 + i] = b_x0[i]; sBias[384 + i] = b_x1[i];
        sBias[512 + i] = w_inf[i];
    }
    for (int i = tid; i < 384; i += 128) { sBias[640 + i] = g_W0c[i]; sBias[1024 + i] = g_Wout[i]; }
    if (tid < 3) sBias[1408 + tid] = b_xo[tid];
    if (tid == 3) sBias[1411] = b_inf[0];

    if (tid < 64) {                      // per-edge geometry
        const int e = eBase + tid;
        const int s = senders[e], rc = receivers[e];
        sRecv[tid] = rc;
        const float* ps = pos + (size_t)s * 9;
        const float* pr = pos + (size_t)rc * 9;
        float* sv = sVec + tid * 16;
#pragma unroll
        for (int v = 0; v < 3; v++) {
            float n2 = 0.f;
#pragma unroll
            for (int dd = 0; dd < 3; dd++) {
                float dv = pr[v * 3 + dd] - ps[v * 3 + dd];
                sv[v * 3 + dd] = dv; n2 += dv * dv;
            }
            sv[9 + v] = (n2 > 0.f) ? sqrtf(n2) : 0.f;
            sv[12 + v] = n2;
        }
    }

    float d[16][4];
    uint32_t ah[8][4];
    const int e0 = eBase + r0, e1 = eBase + r1;

    {   // featS A-frags
        const float* f0 = feat + (size_t)senders[e0] * 128;
        const float* f1 = feat + (size_t)senders[e1] * 128;
#pragma unroll
        for (int kc = 0; kc < 8; kc++) gfrag1(f0, f1, kc, tig, ah);
    }
    waitW1(); __syncthreads();           // T0 ready (T1 may be in flight)

    // ---- L0a (featS x W0[0:128]) on b0 ----
    zero_d(d);
    mma1(d, ah, B0, lane);
    __syncthreads();
    loadW32(a0, g_WF[2], tid);           // T2 = L1.hi -> b0
    {   // featR A-frags
        const float* f0 = feat + (size_t)receivers[e0] * 128;
        const float* f1 = feat + (size_t)receivers[e1] * 128;
#pragma unroll
        for (int kc = 0; kc < 8; kc++) gfrag1(f0, f1, kc, tig, ah);
    }
    waitW1(); __syncthreads();           // T1 ready (T2 in flight)

    // ---- L0b (featR, accumulate) on b1 ----
    mma1(d, ah, B1, lane);
    __syncthreads();
    loadW32(a1, g_WF[3], tid);           // T3 = Lx0.hi -> b1
    {   // L0 epilogue: + bias + sq·w0c, silu -> frags
        const float* svr0 = sVec + r0 * 16;
        const float* svr1 = sVec + r1 * 16;
        float sa0 = svr0[12], sa1 = svr0[13], sa2 = svr0[14];
        float sb0 = svr1[12], sb1 = svr1[13], sb2 = svr1[14];
#pragma unroll
        for (int kc = 0; kc < 8; kc++)
#pragma unroll
            for (int u = 0; u < 2; u++) {
                int j = 2 * kc + u, c = j * 8 + 2 * tig;
                float2 bb = *(const float2*)(sBias + c);
                float2 w0 = *(const float2*)(sBias + 640 + c);
                float2 w1 = *(const float2*)(sBias + 768 + c);
                float2 w2 = *(const float2*)(sBias + 896 + c);
                float v0 = fsilu(d[j][0] + bb.x + sa0 * w0.x + sa1 * w1.x + sa2 * w2.x);
                float v1 = fsilu(d[j][1] + bb.y + sa0 * w0.y + sa1 * w1.y + sa2 * w2.y);
                float v2 = fsilu(d[j][2] + bb.x + sb0 * w0.x + sb1 * w1.x + sb2 * w2.x);
                float v3 = fsilu(d[j][3] + bb.y + sb0 * w0.y + sb1 * w1.y + sb2 * w2.y);
                ah[kc][2 * u]     = pack2(v0, v1);
                ah[kc][2 * u + 1] = pack2(v2, v3);
            }
    }
    waitW1(); __syncthreads();           // T2 ready (T3 in flight)

    // ---- L1 -> m_ij on b0 ----
    zero_d(d);
    mma1(d, ah, B0, lane);
    __syncthreads();
    loadW32(a0, g_WF[4], tid);           // T4 = Lx1.hi -> b0
    {   // L1 epilogue: silu, gate dot, frags, m-scatter
        float s0 = 0.f, s1 = 0.f;
#pragma unroll
        for (int kc = 0; kc < 8; kc++)
#pragma unroll
            for (int u = 0; u < 2; u++) {
                int j = 2 * kc + u, c = j * 8 + 2 * tig;
                float2 bb = *(const float2*)(sBias + 128 + c);
                float2 wf = *(const float2*)(sBias + 512 + c);
                float v0 = fsilu(d[j][0] + bb.x), v1 = fsilu(d[j][1] + bb.y);
                float v2 = fsilu(d[j][2] + bb.x), v3 = fsilu(d[j][3] + bb.y);
                s0 += v0 * wf.x + v1 * wf.y;
                s1 += v2 * wf.x + v3 * wf.y;
                d[j][0] = v0; d[j][1] = v1; d[j][2] = v2; d[j][3] = v3;
                ah[kc][2 * u]     = pack2(v0, v1);
                ah[kc][2 * u + 1] = pack2(v2, v3);
            }
        s0 += __shfl_xor_sync(0xffffffffu, s0, 1); s0 += __shfl_xor_sync(0xffffffffu, s0, 2);
        s1 += __shfl_xor_sync(0xffffffffu, s1, 1); s1 += __shfl_xor_sync(0xffffffffu, s1, 2);
        const float bi = sBias[1411];
        const float g0 = fsigmoid(s0 + bi), g1 = fsigmoid(s1 + bi);
        float* p0 = g_mAcc + (size_t)sRecv[r0] * 128;
        float* p1 = g_mAcc + (size_t)sRecv[r1] * 128;
#pragma unroll
        for (int j = 0; j < 16; j++) {
            int c = j * 8 + 2 * tig;
            red2(p0 + c, d[j][0] * g0, d[j][1] * g0);
            red2(p1 + c, d[j][2] * g1, d[j][3] * g1);
        }
    }
    waitW1(); __syncthreads();           // T3 ready (T4 in flight)

    // ---- Lx0 on b1 ----
    zero_d(d);
    mma1(d, ah, B1, lane);
    {   // Lx0 epilogue
#pragma unroll
        for (int kc = 0; kc < 8; kc++)
#pragma unroll
            for (int u = 0; u < 2; u++) {
                int j = 2 * kc + u, c = j * 8 + 2 * tig;
                float2 bb = *(const float2*)(sBias + 256 + c);
                float v0 = fsilu(d[j][0] + bb.x), v1 = fsilu(d[j][1] + bb.y);
                float v2 = fsilu(d[j][2] + bb.x), v3 = fsilu(d[j][3] + bb.y);
                ah[kc][2 * u]     = pack2(v0, v1);
                ah[kc][2 * u + 1] = pack2(v2, v3);
            }
    }
    waitW0(); __syncthreads();           // T4 ready

    // ---- Lx1 on b0 ----
    zero_d(d);
    mma1(d, ah, B0, lane);
    {   // Lx1 epilogue: phi_x dots + shift scatter
        float pa0 = 0.f, pa1 = 0.f, pa2 = 0.f, pb0 = 0.f, pb1 = 0.f, pb2 = 0.f;
#pragma unroll
        for (int kc = 0; kc < 8; kc++)
#pragma unroll
            for (int u = 0; u < 2; u++) {
                int j = 2 * kc + u, c = j * 8 + 2 * tig;
                float2 bb = *(const float2*)(sBias + 384 + c);
                float2 q0 = *(const float2*)(sBias + 1024 + c);
                float2 q1 = *(const float2*)(sBias + 1152 + c);
                float2 q2 = *(const float2*)(sBias + 1280 + c);
                float v0 = fsilu(d[j][0] + bb.x), v1 = fsilu(d[j][1] + bb.y);
                float v2 = fsilu(d[j][2] + bb.x), v3 = fsilu(d[j][3] + bb.y);
                pa0 += v0 * q0.x + v1 * q0.y; pa1 += v0 * q1.x + v1 * q1.y; pa2 += v0 * q2.x + v1 * q2.y;
                pb0 += v2 * q0.x + v3 * q0.y; pb1 += v2 * q1.x + v3 * q1.y; pb2 += v2 * q2.x + v3 * q2.y;
            }
#pragma unroll
        for (int msk = 1; msk <= 2; msk <<= 1) {
            pa0 += __shfl_xor_sync(0xffffffffu, pa0, msk);
            pa1 += __shfl_xor_sync(0xffffffffu, pa1, msk);
            pa2 += __shfl_xor_sync(0xffffffffu, pa2, msk);
            pb0 += __shfl_xor_sync(0xffffffffu, pb0, msk);
            pb1 += __shfl_xor_sync(0xffffffffu, pb1, msk);
            pb2 += __shfl_xor_sync(0xffffffffu, pb2, msk);
        }
        if (tig == 0) {
            float pv0[3] = { pa0, pa1, pa2 }, pv1[3] = { pb0, pb1, pb2 };
            const float* svr0 = sVec + r0 * 16;
            const float* svr1 = sVec + r1 * 16;
            float* d0 = g_vAcc + (size_t)sRecv[r0] * 9;
            float* d1 = g_vAcc + (size_t)sRecv[r1] * 9;
#pragma unroll
            for (int v = 0; v < 3; v++) {
                float sc0 = (pv0[v] + sBias[1408 + v]) * frcp(1.0f + svr0[9 + v]);
                float sc1 = (pv1[v] + sBias[1408 + v]) * frcp(1.0f + svr1[9 + v]);
#pragma unroll
                for (int dd = 0; dd < 3; dd++) {
                    atomicAdd(d0 + v * 3 + dd, sc0 * svr0[v * 3 + dd]);
                    atomicAdd(d1 + v * 3 + dd, sc1 * svr1[v * 3 + dd]);
                }
            }
        }
    }
}

// ======== node kernel: 64 nodes / 4 warps, full 3-pass, 2 blocks per SM ========
extern "C" __global__ void __launch_bounds__(128, 2)
node_kernel(const float* __restrict__ pos, const float* __restrict__ feat,
            const float* __restrict__ b_h0, const float* __restrict__ b_h1,
            const float* __restrict__ b_h2, float* __restrict__ out)
{
    extern __shared__ __align__(16) float sm[];
    const uint32_t sA = smem_u32(sm);
    const int tid = threadIdx.x, lane = tid & 31, warp = tid >> 5;
    const int g = lane >> 2, tig = lane & 3;
    const int r0 = warp * 16 + g, r1 = r0 + 8;
    const int nBase = blockIdx.x * 64;
    const int node0 = nBase + r0, node1 = nBase + r1;
    const bool va = node0 < N_NODES, vb = node1 < N_NODES;
    const uint32_t* B0 = (const uint32_t*)sm;
    const uint32_t* B1 = B0 + 8192;
    const uint32_t* B2 = B0 + 16384;
    const uint32_t a0 = sA, a1 = sA + 32768, a2 = sA + 65536;
    float* sBias = sm + NF_BIAS;

    loadW32(a0, g_WF[5], tid);           // T5.hi
    loadW32(a1, g_WF[5] + 8192, tid);    // T5.lo
    loadW32(a2, g_WF[6], tid);           // T6.hi
    for (int i = tid; i < 128; i += 128) {
        sBias[i] = b_h0[i]; sBias[128 + i] = b_h1[i]; sBias[256 + i] = b_h2[i];
    }
    const float invNN = 1.0f / 19999.0f;
    for (int idx = tid; idx < 64 * 9; idx += 128) {
        const int i = idx / 9, c = idx - i * 9;
        const int n = nBase + i;
        if (n < N_NODES)
            out[(size_t)n * 9 + c] = pos[(size_t)n * 9 + c] + g_vAcc[(size_t)n * 9 + c] * invNN;
    }

    float d[16][4];
    uint32_t ah[8][4], al[8][4];
    const float invSq = rsqrtf(19999.0f);
    {   // m_i * invSq frags
        const float* f0 = g_mAcc + (size_t)(va ? node0 : 0) * 128;
        const float* f1 = g_mAcc + (size_t)(vb ? node1 : 0) * 128;
#pragma unroll
        for (int kc = 0; kc < 8; kc++) gfrag(f0, f1, kc, tig, ah, al, va, vb, invSq);
    }
    waitW1(); __syncthreads();

    // ---- T5 = H0a (m_i), rotation (0,1,2) ----
    zero_d(d);
    mma12(d, ah, al, B0, lane);
    __syncthreads();
    loadW32(a0, g_WF[6] + 8192, tid);    // T6.lo -> b0
    mma3(d, ah, B1, lane);
    {   // feat frags
        const float* f0 = feat + (size_t)(va ? node0 : 0) * 128;
        const float* f1 = feat + (size_t)(vb ? node1 : 0) * 128;
#pragma unroll
        for (int kc = 0; kc < 8; kc++) gfrag(f0, f1, kc, tig, ah, al, va, vb, 1.f);
    }
    waitW0(); __syncthreads();

    // ---- T6 = H0b (feat, accumulate), rotation (2,0,1) ----
    loadW32(a1, g_WF[7], tid);           // T7.hi -> b1
    mma12(d, ah, al, B2, lane);
    __syncthreads();
    loadW32(a2, g_WF[7] + 8192, tid);    // T7.lo -> b2
    mma3(d, ah, B0, lane);
#pragma unroll
    for (int kc = 0; kc < 8; kc++)        // h0 epilogue
#pragma unroll
        for (int u = 0; u < 2; u++) {
            int j = 2 * kc + u, c = j * 8 + 2 * tig;
            float2 bb = *(const float2*)(sBias + c);
            float v0 = fsilu(d[j][0] + bb.x), v1 = fsilu(d[j][1] + bb.y);
            float v2 = fsilu(d[j][2] + bb.x), v3 = fsilu(d[j][3] + bb.y);
            split2(v0, v1, ah[kc][2 * u], al[kc][2 * u]);
            split2(v2, v3, ah[kc][2 * u + 1], al[kc][2 * u + 1]);
        }
    waitW0(); __syncthreads();

    // ---- T7 = H1, rotation (1,2,0) ----
    loadW32(a0, g_WF[8], tid);           // T8.hi -> b0
    zero_d(d);
    mma12(d, ah, al, B1, lane);
    __syncthreads();
    loadW32(a1, g_WF[8] + 8192, tid);    // T8.lo -> b1
    mma3(d, ah, B2, lane);
#pragma unroll
    for (int kc = 0; kc < 8; kc++)        // h1 epilogue
#pragma unroll
        for (int u = 0; u < 2; u++) {
            int j = 2 * kc + u, c = j * 8 + 2 * tig;
            float2 bb = *(const float2*)(sBias + 128 + c);
            float v0 = fsilu(d[j][0] + bb.x), v1 = fsilu(d[j][1] + bb.y);
            float v2 = fsilu(d[j][2] + bb.x), v3 = fsilu(d[j][3] + bb.y);
            split2(v0, v1, ah[kc][2 * u], al[kc][2 * u]);
            split2(v2, v3, ah[kc][2 * u + 1], al[kc][2 * u + 1]);
        }
    waitW0(); __syncthreads();

    // ---- T8 = H2, rotation (0,1,2) ----
    zero_d(d);
    mma12(d, ah, al, B0, lane);
    mma3(d, ah, B1, lane);
    // h2 + residual -> out
#pragma unroll
    for (int j = 0; j < 16; j++) {
        int c = j * 8 + 2 * tig;
        float2 bb = *(const float2*)(sBias + 256 + c);
        if (va) {
            float2 f = __ldg((const float2*)(feat + (size_t)node0 * 128 + c));
            float2 o = make_float2(d[j][0] + bb.x + f.x, d[j][1] + bb.y + f.y);
            *(float2*)(out + VOFF + (size_t)node0 * 128 + c) = o;
        }
        if (vb) {
            float2 f = __ldg((const float2*)(feat + (size_t)node1 * 128 + c));
            float2 o = make_float2(d[j][2] + bb.x + f.x, d[j][3] + bb.y + f.y);
            *(float2*)(out + VOFF + (size_t)node1 * 128 + c) = o;
        }
    }
}

// ======================= prep + zero =======================
__global__ void prep_kernel(const float* __restrict__ w_e0, const float* __restrict__ w_e1,
                            const float* __restrict__ w_x0, const float* __restrict__ w_x1,
                            const float* __restrict__ w_xo,
                            const float* __restrict__ w_h0, const float* __restrict__ w_h1,
                            const float* __restrict__ w_h2)
{
    const int idx = blockIdx.x * blockDim.x + threadIdx.x;
    const int stride = gridDim.x * blockDim.x;
    const float* srcs[9] = { w_e0, w_e0, w_e1, w_x0, w_x1, w_h0, w_h0, w_h1, w_h2 };
    const int koff[9] = { 0, 128, 0, 0, 0, 0, 128, 0, 0 };
    for (int i = idx; i < 9 * 8192; i += stride) {
        const int t = i >> 13, fi = i & 8191;
        const int ri = fi & 1, ln = (fi >> 1) & 31, j = (fi >> 6) & 15, kc = fi >> 10;
        const int tg = ln & 3, gg = ln >> 2;
        const int k = kc * 16 + ri * 8 + tg * 2;
        const int n = j * 8 + gg;
        const float* s = srcs[t];
        const float wa = s[(size_t)(koff[t] + k) * 128 + n];
        const float wb = s[(size_t)(koff[t] + k + 1) * 128 + n];
        const __half ha = __float2half_rn(wa), hb = __float2half_rn(wb);
        const __half la = __float2half_rn(wa - __half2float(ha));
        const __half lb = __float2half_rn(wb - __half2float(hb));
        g_WF[t][fi] = (uint32_t)__half_as_ushort(ha) | ((uint32_t)__half_as_ushort(hb) << 16);
        g_WF[t][8192 + fi] = (uint32_t)__half_as_ushort(la) | ((uint32_t)__half_as_ushort(lb) << 16);
    }
    for (int i = idx; i < 384; i += stride) {
        const int v = i >> 7, k = i & 127;
        g_W0c[i]  = w_e0[(size_t)(256 + v) * 128 + k];
        g_Wout[i] = w_xo[(size_t)k * 3 + v];
    }
}

__global__ void zero_kernel()
{
    const int idx = blockIdx.x * blockDim.x + threadIdx.x;
    const int stride = gridDim.x * blockDim.x;
    for (int i = idx; i < N_NODES * 128; i += stride) g_mAcc[i] = 0.f;
    for (int i = idx; i < N_NODES * 9; i += stride)   g_vAcc[i] = 0.f;
}

// ======================= launch =======================
extern "C" void kernel_launch(void* const* d_in, const int* in_sizes, int n_in,
                              void* d_out, int out_size)
{
    (void)in_sizes; (void)n_in; (void)out_size;
    const float* pos  = (const float*)d_in[0];
    const float* feat = (const float*)d_in[1];
    const int* senders   = (const int*)d_in[2];
    const int* receivers = (const int*)d_in[3];
    const float* w_e0 = (const float*)d_in[4];  const float* b_e0 = (const float*)d_in[5];
    const float* w_e1 = (const float*)d_in[6];  const float* b_e1 = (const float*)d_in[7];
    const float* w_x0 = (const float*)d_in[8];  const float* b_x0 = (const float*)d_in[9];
    const float* w_x1 = (const float*)d_in[10]; const float* b_x1 = (const float*)d_in[11];
    const float* w_xo = (const float*)d_in[12]; const float* b_xo = (const float*)d_in[13];
    const float* w_if = (const float*)d_in[14]; const float* b_if = (const float*)d_in[15];
    const float* w_h0 = (const float*)d_in[16]; const float* b_h0 = (const float*)d_in[17];
    const float* w_h1 = (const float*)d_in[18]; const float* b_h1 = (const float*)d_in[19];
    const float* w_h2 = (const float*)d_in[20]; const float* b_h2 = (const float*)d_in[21];
    float* out = (float*)d_out;

    cudaFuncSetAttribute(edge_kernel, cudaFuncAttributeMaxDynamicSharedMemorySize, ESM_BYTES);
    cudaFuncSetAttribute(node_kernel, cudaFuncAttributeMaxDynamicSharedMemorySize, NSM_BYTES);

    prep_kernel<<<128, 256>>>(w_e0, w_e1, w_x0, w_x1, w_xo, w_h0, w_h1, w_h2);
    zero_kernel<<<256, 256>>>();
    edge_kernel<<<E_EDGES / 64, 128, ESM_BYTES>>>(pos, feat, senders, receivers,
                                                  b_e0, b_e1, b_x0, b_x1, b_xo, w_if, b_if);
    node_kernel<<<(N_NODES + 63) / 64, 128, NSM_BYTES>>>(pos, feat, b_h0, b_h1, b_h2, out);
}